// round 1
// baseline (speedup 1.0000x reference)
#include <cuda_runtime.h>
#include <math.h>

// Problem constants
#define BB   8
#define SS   4096
#define EE   512
#define PP   64
#define LL   4
#define HH   256
#define CC   2
#define FF   2048               // 4*E
#define MROWS (BB*SS)           // 32768

// ---------------- scratch (device globals; allocation-free) ----------------
__device__ float g_H  [(size_t)MROWS*EE];   // hidden / residual stream
__device__ float g_A  [(size_t)MROWS*EE];   // attn out -> layernorm (in place)
__device__ float g_V  [(size_t)MROWS*EE];   // v projection
__device__ float g_NUM[(size_t)MROWS*EE];   // attn = num/den
__device__ float g_M  [(size_t)MROWS*FF];   // MLP intermediate
__device__ float g_Q  [(size_t)MROWS*PP];
__device__ float g_K  [(size_t)MROWS*PP];
__device__ float g_KV [(size_t)BB*PP*EE];
__device__ float g_Z  [(size_t)BB*PP];

// ---------------- embedding + positional ----------------
__global__ void embed_kernel(const int* __restrict__ x,
                             const float* __restrict__ emb,
                             const float* __restrict__ pos,
                             float* __restrict__ H) {
    int row = blockIdx.x;                  // 0..MROWS-1
    int s   = row & (SS - 1);
    int tok = x[row];
    const float4* e4 = (const float4*)(emb + (size_t)tok * EE);
    const float4* p4 = (const float4*)(pos + (size_t)s * EE);
    float4* h4 = (float4*)(H + (size_t)row * EE);
    int t = threadIdx.x;                   // 128 threads, EE/4 = 128
    float4 a = e4[t], b = p4[t];
    h4[t] = make_float4(a.x + b.x, a.y + b.y, a.z + b.z, a.w + b.w);
}

// ---------------- generic tiled SGEMM with fused epilogues ----------------
enum { EPI_NONE = 0, EPI_PHI = 1, EPI_GELU = 2, EPI_RES = 3 };

template<int BM, int BN, int BK, int TM, int TN, int EPI>
__global__ void __launch_bounds__(256)
gemm_kernel(int M, int N, int K,
            const float* __restrict__ A,      // [M,K] row-major
            const float* __restrict__ B,      // [K,N] row-major
            const float* __restrict__ bias,   // [N] or null
            const float* __restrict__ res,    // [M,N] or null
            float* __restrict__ C)            // [M,N]
{
    __shared__ float As[BK * BM];   // transposed: As[k][m]
    __shared__ float Bs[BK * BN];

    const int tid  = threadIdx.x;
    const int row0 = blockIdx.y * BM;
    const int col0 = blockIdx.x * BN;
    const int tx   = tid % (BN / TN);
    const int ty   = tid / (BN / TN);

    constexpr int NT   = 256;
    constexpr int A_V4 = BM * BK / (4 * NT);
    constexpr int B_V4 = BK * BN / (4 * NT);

    float acc[TM][TN];
    #pragma unroll
    for (int i = 0; i < TM; i++)
        #pragma unroll
        for (int j = 0; j < TN; j++) acc[i][j] = 0.f;

    for (int k0 = 0; k0 < K; k0 += BK) {
        #pragma unroll
        for (int i = 0; i < A_V4; i++) {
            int idx = tid + i * NT;
            int r   = idx / (BK / 4);
            int c4  = idx % (BK / 4);
            float4 v = *(const float4*)(A + (size_t)(row0 + r) * K + k0 + c4 * 4);
            As[(c4 * 4 + 0) * BM + r] = v.x;
            As[(c4 * 4 + 1) * BM + r] = v.y;
            As[(c4 * 4 + 2) * BM + r] = v.z;
            As[(c4 * 4 + 3) * BM + r] = v.w;
        }
        #pragma unroll
        for (int i = 0; i < B_V4; i++) {
            int idx = tid + i * NT;
            int r   = idx / (BN / 4);
            int c4  = idx % (BN / 4);
            *(float4*)(Bs + r * BN + c4 * 4) =
                *(const float4*)(B + (size_t)(k0 + r) * N + col0 + c4 * 4);
        }
        __syncthreads();

        #pragma unroll
        for (int k = 0; k < BK; k++) {
            float ra[TM], rb[TN];
            #pragma unroll
            for (int i = 0; i < TM / 4; i++)
                *(float4*)(ra + i * 4) = *(const float4*)(As + k * BM + ty * TM + i * 4);
            #pragma unroll
            for (int j = 0; j < TN / 4; j++)
                *(float4*)(rb + j * 4) = *(const float4*)(Bs + k * BN + tx * TN + j * 4);
            #pragma unroll
            for (int i = 0; i < TM; i++)
                #pragma unroll
                for (int j = 0; j < TN; j++)
                    acc[i][j] = fmaf(ra[i], rb[j], acc[i][j]);
        }
        __syncthreads();
    }

    #pragma unroll
    for (int i = 0; i < TM; i++) {
        int r = row0 + ty * TM + i;
        #pragma unroll
        for (int j = 0; j < TN; j++) {
            int c = col0 + tx * TN + j;
            float v = acc[i][j];
            if (EPI == EPI_PHI) {
                // elu(x)+1 : x>0 -> x+1 ; else exp(x)
                v = v > 0.f ? v + 1.f : expf(v);
            } else if (EPI == EPI_GELU) {
                v += bias[c];
                float u = 0.7978845608028654f * (v + 0.044715f * v * v * v);
                v = 0.5f * v * (1.f + tanhf(u));
            } else if (EPI == EPI_RES) {
                v += bias[c] + res[(size_t)r * N + c];
            }
            C[(size_t)r * N + c] = v;
        }
    }
}

// ---------------- kv = sum_s phi_k[s,p] * v[s,f]  (per batch) ----------------
// grid: (E/64, B), block 256, each block computes the full 64(p) x 64(f) tile.
__global__ void __launch_bounds__(256)
kv_kernel(const float* __restrict__ Kp, const float* __restrict__ V,
          float* __restrict__ KV)
{
    int b  = blockIdx.y;
    int f0 = blockIdx.x * 64;
    const float* Kb = Kp + (size_t)b * SS * PP;
    const float* Vb = V  + (size_t)b * SS * EE;

    __shared__ float Ks[32 * 64];   // [s][p]
    __shared__ float Vs[32 * 64];   // [s][f]
    int tid = threadIdx.x;
    int tx = tid % 16, ty = tid / 16;

    float acc[4][4];
    #pragma unroll
    for (int i = 0; i < 4; i++)
        #pragma unroll
        for (int j = 0; j < 4; j++) acc[i][j] = 0.f;

    for (int s0 = 0; s0 < SS; s0 += 32) {
        #pragma unroll
        for (int i = 0; i < 2; i++) {
            int idx = tid + i * 256;
            int r = idx / 16, c4 = idx % 16;
            *(float4*)(Ks + r * 64 + c4 * 4) =
                *(const float4*)(Kb + (size_t)(s0 + r) * PP + c4 * 4);
            *(float4*)(Vs + r * 64 + c4 * 4) =
                *(const float4*)(Vb + (size_t)(s0 + r) * EE + f0 + c4 * 4);
        }
        __syncthreads();
        #pragma unroll
        for (int k = 0; k < 32; k++) {
            float rp[4], rv[4];
            #pragma unroll
            for (int i = 0; i < 4; i++) rp[i] = Ks[k * 64 + ty * 4 + i];
            #pragma unroll
            for (int j = 0; j < 4; j++) rv[j] = Vs[k * 64 + tx * 4 + j];
            #pragma unroll
            for (int i = 0; i < 4; i++)
                #pragma unroll
                for (int j = 0; j < 4; j++)
                    acc[i][j] = fmaf(rp[i], rv[j], acc[i][j]);
        }
        __syncthreads();
    }
    #pragma unroll
    for (int i = 0; i < 4; i++)
        #pragma unroll
        for (int j = 0; j < 4; j++)
            KV[((size_t)b * PP + ty * 4 + i) * EE + f0 + tx * 4 + j] = acc[i][j];
}

// ---------------- z = sum_s phi_k[s,p] (per batch) ----------------
__global__ void z_kernel(const float* __restrict__ Kp, float* __restrict__ Z) {
    int b = blockIdx.x;
    int tid = threadIdx.x;                 // 256
    int p = tid & 63, g = tid >> 6;
    const float* Kb = Kp + (size_t)b * SS * PP;
    float acc = 0.f;
    for (int s = g; s < SS; s += 4) acc += Kb[(size_t)s * PP + p];
    __shared__ float sm[256];
    sm[tid] = acc;
    __syncthreads();
    if (g == 0) Z[b * PP + p] = sm[p] + sm[64 + p] + sm[128 + p] + sm[192 + p];
}

// ---------------- attn = (phi_q @ KV) / (phi_q . z + eps) ----------------
// grid: (E/128, S/64, B), block 256. K dim = 64 (fits fully in smem).
__global__ void __launch_bounds__(256)
num_kernel(const float* __restrict__ Qp, const float* __restrict__ KV,
           const float* __restrict__ Z, float* __restrict__ OUT)
{
    int b  = blockIdx.z;
    int s0 = blockIdx.y * 64;
    int f0 = blockIdx.x * 128;

    __shared__ float Qs[64 * 64];     // [s][p]
    __shared__ float KVs[64 * 128];   // [p][f]
    __shared__ float Zs[64];

    int tid = threadIdx.x;
    const float* Qb = Qp + ((size_t)b * SS + s0) * PP;
    #pragma unroll
    for (int i = 0; i < 4; i++) {
        int idx = tid + i * 256;
        int r = idx / 16, c4 = idx % 16;
        *(float4*)(Qs + r * 64 + c4 * 4) =
            *(const float4*)(Qb + (size_t)r * PP + c4 * 4);
    }
    const float* KVb = KV + (size_t)b * PP * EE;
    #pragma unroll
    for (int i = 0; i < 8; i++) {
        int idx = tid + i * 256;
        int r = idx / 32, c4 = idx % 32;
        *(float4*)(KVs + r * 128 + c4 * 4) =
            *(const float4*)(KVb + (size_t)r * EE + f0 + c4 * 4);
    }
    if (tid < 64) Zs[tid] = Z[b * PP + tid];
    __syncthreads();

    int tx = tid % 16, ty = tid / 16;  // 16 f-groups of 8, 16 s-groups of 4
    float acc[4][8];
    float den[4] = {0.f, 0.f, 0.f, 0.f};
    #pragma unroll
    for (int i = 0; i < 4; i++)
        #pragma unroll
        for (int j = 0; j < 8; j++) acc[i][j] = 0.f;

    #pragma unroll 8
    for (int k = 0; k < 64; k++) {
        float rq[4];
        #pragma unroll
        for (int i = 0; i < 4; i++) rq[i] = Qs[(ty * 4 + i) * 64 + k];
        float rz = Zs[k];
        #pragma unroll
        for (int i = 0; i < 4; i++) den[i] = fmaf(rq[i], rz, den[i]);
        #pragma unroll
        for (int j = 0; j < 8; j++) {
            float rk = KVs[k * 128 + tx * 8 + j];
            #pragma unroll
            for (int i = 0; i < 4; i++) acc[i][j] = fmaf(rq[i], rk, acc[i][j]);
        }
    }

    float* Ob = OUT + ((size_t)b * SS + s0) * EE;
    #pragma unroll
    for (int i = 0; i < 4; i++) {
        float inv = 1.f / (den[i] + 1e-6f);
        #pragma unroll
        for (int j = 0; j < 8; j++)
            Ob[(size_t)(ty * 4 + i) * EE + f0 + tx * 8 + j] = acc[i][j] * inv;
    }
}

// ---------------- layernorm (in place), one block per row ----------------
__global__ void ln_kernel(float* __restrict__ X,
                          const float* __restrict__ gam,
                          const float* __restrict__ bet) {
    int row = blockIdx.x;
    float* xr = X + (size_t)row * EE;
    int tid = threadIdx.x;                 // 128
    float4 v = ((float4*)xr)[tid];
    float s = v.x + v.y + v.z + v.w;
    float q = v.x * v.x + v.y * v.y + v.z * v.z + v.w * v.w;
    #pragma unroll
    for (int o = 16; o; o >>= 1) {
        s += __shfl_xor_sync(0xffffffffu, s, o);
        q += __shfl_xor_sync(0xffffffffu, q, o);
    }
    __shared__ float ss[4], qq[4];
    int w = tid >> 5;
    if ((tid & 31) == 0) { ss[w] = s; qq[w] = q; }
    __syncthreads();
    s = ss[0] + ss[1] + ss[2] + ss[3];
    q = qq[0] + qq[1] + qq[2] + qq[3];
    float mu  = s * (1.f / EE);
    float var = q * (1.f / EE) - mu * mu;
    float inv = rsqrtf(var + 1e-5f);
    float4 g4 = ((const float4*)gam)[tid];
    float4 b4 = ((const float4*)bet)[tid];
    float4 o;
    o.x = (v.x - mu) * inv * g4.x + b4.x;
    o.y = (v.y - mu) * inv * g4.y + b4.y;
    o.z = (v.z - mu) * inv * g4.z + b4.z;
    o.w = (v.w - mu) * inv * g4.w + b4.w;
    ((float4*)xr)[tid] = o;
}

// ---------------- head: relu(h[:,0,:] @ Wh1 + bh1) @ Wh2 + bh2 ----------------
__global__ void head_kernel(const float* __restrict__ Hm,
                            const float* __restrict__ Wh1,
                            const float* __restrict__ bh1,
                            const float* __restrict__ Wh2,
                            const float* __restrict__ bh2,
                            float* __restrict__ out) {
    int b = blockIdx.x;
    int tid = threadIdx.x;                 // 256 = HH
    const float* hr = Hm + (size_t)b * SS * EE;   // h[b, 0, :]
    float acc = bh1[tid];
    for (int e = 0; e < EE; e++) acc = fmaf(hr[e], Wh1[e * HH + tid], acc);
    acc = fmaxf(acc, 0.f);
    __shared__ float hid[HH];
    hid[tid] = acc;
    __syncthreads();
    if (tid < CC) {
        float a = bh2[tid];
        for (int h = 0; h < HH; h++) a = fmaf(hid[h], Wh2[h * CC + tid], a);
        out[b * CC + tid] = a;
    }
}

// ---------------- launch ----------------
extern "C" void kernel_launch(void* const* d_in, const int* in_sizes, int n_in,
                              void* d_out, int out_size) {
    const int*   x    = (const int*)  d_in[0];
    const float* emb  = (const float*)d_in[1];
    const float* pos  = (const float*)d_in[2];
    const float* Wq   = (const float*)d_in[3];
    const float* Wk   = (const float*)d_in[4];
    const float* Wv   = (const float*)d_in[5];
    const float* Wo   = (const float*)d_in[6];
    const float* ln_g = (const float*)d_in[7];
    const float* ln_b = (const float*)d_in[8];
    const float* W1   = (const float*)d_in[9];
    const float* b1   = (const float*)d_in[10];
    const float* W2   = (const float*)d_in[11];
    const float* b2   = (const float*)d_in[12];
    const float* Wh1  = (const float*)d_in[13];
    const float* bh1  = (const float*)d_in[14];
    const float* Wh2  = (const float*)d_in[15];
    const float* bh2  = (const float*)d_in[16];
    float* out = (float*)d_out;

    float *H, *A, *V, *NUM, *Mb, *Q, *Kq, *KV, *Z;
    cudaGetSymbolAddress((void**)&H,   g_H);
    cudaGetSymbolAddress((void**)&A,   g_A);
    cudaGetSymbolAddress((void**)&V,   g_V);
    cudaGetSymbolAddress((void**)&NUM, g_NUM);
    cudaGetSymbolAddress((void**)&Mb,  g_M);
    cudaGetSymbolAddress((void**)&Q,   g_Q);
    cudaGetSymbolAddress((void**)&Kq,  g_K);
    cudaGetSymbolAddress((void**)&KV,  g_KV);
    cudaGetSymbolAddress((void**)&Z,   g_Z);

    embed_kernel<<<MROWS, 128>>>(x, emb, pos, H);

    for (int l = 0; l < LL; l++) {
        const float* Wql = Wq + (size_t)l * EE * PP;
        const float* Wkl = Wk + (size_t)l * EE * PP;
        const float* Wvl = Wv + (size_t)l * EE * EE;
        const float* Wol = Wo + (size_t)l * EE * EE;
        const float* W1l = W1 + (size_t)l * EE * FF;
        const float* W2l = W2 + (size_t)l * FF * EE;

        // q, k projections with fused phi = elu+1
        gemm_kernel<128, 64, 16, 8, 4, EPI_PHI>
            <<<dim3(PP / 64, MROWS / 128), 256>>>(MROWS, PP, EE, H, Wql, nullptr, nullptr, Q);
        gemm_kernel<128, 64, 16, 8, 4, EPI_PHI>
            <<<dim3(PP / 64, MROWS / 128), 256>>>(MROWS, PP, EE, H, Wkl, nullptr, nullptr, Kq);
        // v projection
        gemm_kernel<128, 128, 8, 8, 8, EPI_NONE>
            <<<dim3(EE / 128, MROWS / 128), 256>>>(MROWS, EE, EE, H, Wvl, nullptr, nullptr, V);

        kv_kernel<<<dim3(EE / 64, BB), 256>>>(Kq, V, KV);
        z_kernel<<<BB, 256>>>(Kq, Z);
        num_kernel<<<dim3(EE / 128, SS / 64, BB), 256>>>(Q, KV, Z, NUM);

        // output projection
        gemm_kernel<128, 128, 8, 8, 8, EPI_NONE>
            <<<dim3(EE / 128, MROWS / 128), 256>>>(MROWS, EE, EE, NUM, Wol, nullptr, nullptr, A);

        ln_kernel<<<MROWS, 128>>>(A, ln_g + (size_t)l * EE, ln_b + (size_t)l * EE);

        // MLP
        gemm_kernel<128, 128, 8, 8, 8, EPI_GELU>
            <<<dim3(FF / 128, MROWS / 128), 256>>>(MROWS, FF, EE, A, W1l,
                                                   b1 + (size_t)l * FF, nullptr, Mb);
        gemm_kernel<128, 128, 8, 8, 8, EPI_RES>
            <<<dim3(EE / 128, MROWS / 128), 256>>>(MROWS, EE, FF, Mb, W2l,
                                                   b2 + (size_t)l * EE, H, H);
    }

    head_kernel<<<BB, HH>>>(H, Wh1, bh1, Wh2, bh2, out);
}

// round 3
// speedup vs baseline: 2.2378x; 2.2378x over previous
#include <cuda_runtime.h>
#include <math.h>

// Problem constants
#define BB   8
#define SS   4096
#define EE   512
#define PP   64
#define LL   4
#define HH   256
#define CC   2
#define FF   2048               // 4*E
#define MROWS (BB*SS)           // 32768

enum { EPI_NONE = 0, EPI_PHI = 1, EPI_GELU = 2, EPI_RES = 3 };

// ---------------- scratch (device globals; allocation-free) ----------------
__device__ float g_H  [(size_t)MROWS*EE];
__device__ float g_A  [(size_t)MROWS*EE];
__device__ float g_V  [(size_t)MROWS*EE];
__device__ float g_NUM[(size_t)MROWS*EE];
__device__ float g_M  [(size_t)MROWS*FF];
__device__ float g_Q  [(size_t)MROWS*PP];
__device__ float g_K  [(size_t)MROWS*PP];
__device__ float g_KV [(size_t)BB*PP*EE];
__device__ float g_Z  [(size_t)BB*PP];

// ---------------- helpers ----------------
__device__ __forceinline__ void cp_async16(void* smem, const void* gmem) {
    unsigned sa = (unsigned)__cvta_generic_to_shared(smem);
    asm volatile("cp.async.cg.shared.global [%0], [%1], 16;" :: "r"(sa), "l"(gmem));
}
__device__ __forceinline__ void cp_commit() {
    asm volatile("cp.async.commit_group;");
}
template<int N>
__device__ __forceinline__ void cp_wait() {
    asm volatile("cp.async.wait_group %0;" :: "n"(N));
}

// Split two consecutive fp32 values into packed bf16x2 hi and lo parts.
// Packing: low 16 bits = first (even-k) element, high 16 bits = second.
__device__ __forceinline__ void split2(float x, float y, unsigned& hi, unsigned& lo) {
    asm("cvt.rn.bf16x2.f32 %0, %1, %2;" : "=r"(hi) : "f"(y), "f"(x));
    float hx = __uint_as_float(hi << 16);
    float hy = __uint_as_float(hi & 0xFFFF0000u);
    float lx = x - hx;
    float ly = y - hy;
    asm("cvt.rn.bf16x2.f32 %0, %1, %2;" : "=r"(lo) : "f"(ly), "f"(lx));
}

__device__ __forceinline__ void mma_bf16(float c[4], const unsigned a[4], const unsigned b[2]) {
    asm volatile(
        "mma.sync.aligned.m16n8k16.row.col.f32.bf16.bf16.f32 "
        "{%0,%1,%2,%3}, {%4,%5,%6,%7}, {%8,%9}, {%0,%1,%2,%3};"
        : "+f"(c[0]), "+f"(c[1]), "+f"(c[2]), "+f"(c[3])
        : "r"(a[0]), "r"(a[1]), "r"(a[2]), "r"(a[3]), "r"(b[0]), "r"(b[1]));
}

// ---------------- embedding + positional ----------------
__global__ void embed_kernel(const int* __restrict__ x,
                             const float* __restrict__ emb,
                             const float* __restrict__ pos,
                             float* __restrict__ H) {
    int row = blockIdx.x;
    int s   = row & (SS - 1);
    int tok = x[row];
    const float4* e4 = (const float4*)(emb + (size_t)tok * EE);
    const float4* p4 = (const float4*)(pos + (size_t)s * EE);
    float4* h4 = (float4*)(H + (size_t)row * EE);
    int t = threadIdx.x;
    float4 a = e4[t], b = p4[t];
    h4[t] = make_float4(a.x + b.x, a.y + b.y, a.z + b.z, a.w + b.w);
}

// ---------------- bf16x2 split-precision tensor-core GEMM ----------------
// C[M,N] = A[M,K] @ B[K,N], row-major, BK = 32, 3-stage cp.async pipeline.
// Each k16 slice: 3x mma.m16n8k16.bf16 (hi*hi + hi*lo + lo*hi), fp32 accum.
template<int BM, int BN, int WM, int WN, int EPI>
__global__ void __launch_bounds__((BM/WM)*(BN/WN)*32)
gemm_b16x2(int M, int N, int K,
           const float* __restrict__ A,
           const float* __restrict__ B,
           const float* __restrict__ bias,
           const float* __restrict__ res,
           float* __restrict__ C)
{
    constexpr int BK = 32;
    constexpr int WARPS_M = BM / WM;
    constexpr int WARPS_N = BN / WN;
    constexpr int NTH = WARPS_M * WARPS_N * 32;
    constexpr int LDA_S = BK + 8;     // As[m][k] stride 40 -> conflict-free float2 frag loads
    constexpr int LDB_S = BN + 4;     // Bs[k][n] stride BN+4 -> conflict-free scalar frag loads
    constexpr int AS_W = BM * LDA_S;
    constexpr int BS_W = BK * LDB_S;
    constexpr int MT = WM / 16;
    constexpr int NT = WN / 8;
    constexpr int LDA_CNT = BM * BK / (4 * NTH);
    constexpr int LDB_CNT = BK * BN / (4 * NTH);

    extern __shared__ float sm[];
    float* As = sm;                 // 3 stages
    float* Bs = sm + 3 * AS_W;

    const int tid  = threadIdx.x;
    const int lane = tid & 31;
    const int warp = tid >> 5;
    const int wm   = warp / WARPS_N;
    const int wn   = warp % WARPS_N;
    const int lr   = lane >> 2;     // 0..7
    const int lc   = lane & 3;      // 0..3
    const int row0 = blockIdx.y * BM;
    const int col0 = blockIdx.x * BN;
    const int KT   = K / BK;

    float acc[MT][NT][4];
    #pragma unroll
    for (int i = 0; i < MT; i++)
        #pragma unroll
        for (int j = 0; j < NT; j++)
            #pragma unroll
            for (int q = 0; q < 4; q++) acc[i][j][q] = 0.f;

    auto issue = [&](int kt, int st) {
        const float* Ag = A + (size_t)row0 * K + kt * BK;
        #pragma unroll
        for (int i = 0; i < LDA_CNT; i++) {
            int idx = tid + i * NTH;
            int r = idx >> 3;           // idx / (BK/4)
            int c4 = idx & 7;
            cp_async16(As + st * AS_W + r * LDA_S + c4 * 4,
                       Ag + (size_t)r * K + c4 * 4);
        }
        const float* Bg = B + (size_t)(kt * BK) * N + col0;
        #pragma unroll
        for (int i = 0; i < LDB_CNT; i++) {
            int idx = tid + i * NTH;
            int r = idx / (BN / 4);
            int c4 = idx % (BN / 4);
            cp_async16(Bs + st * BS_W + r * LDB_S + c4 * 4,
                       Bg + (size_t)r * N + c4 * 4);
        }
    };

    auto compute = [&](int st) {
        const float* Ac = As + st * AS_W;
        const float* Bc = Bs + st * BS_W;
        #pragma unroll
        for (int kk = 0; kk < 2; kk++) {        // two k16 slices per BK=32
            unsigned ah[MT][4], al[MT][4];
            unsigned bh[NT][2], bl[NT][2];
            #pragma unroll
            for (int i = 0; i < MT; i++) {
                const float* p = Ac + (size_t)(wm * WM + i * 16 + lr) * LDA_S + kk * 16 + 2 * lc;
                float2 x0 = *(const float2*)p;                       // row lr,   k 2lc..
                float2 x1 = *(const float2*)(p + 8 * LDA_S);         // row lr+8
                float2 x2 = *(const float2*)(p + 8);                 // k +8
                float2 x3 = *(const float2*)(p + 8 * LDA_S + 8);
                split2(x0.x, x0.y, ah[i][0], al[i][0]);
                split2(x1.x, x1.y, ah[i][1], al[i][1]);
                split2(x2.x, x2.y, ah[i][2], al[i][2]);
                split2(x3.x, x3.y, ah[i][3], al[i][3]);
            }
            #pragma unroll
            for (int j = 0; j < NT; j++) {
                const float* q = Bc + (size_t)(kk * 16 + 2 * lc) * LDB_S + wn * WN + j * 8 + lr;
                float y0 = q[0];
                float y1 = q[LDB_S];
                float y2 = q[8 * LDB_S];
                float y3 = q[9 * LDB_S];
                split2(y0, y1, bh[j][0], bl[j][0]);
                split2(y2, y3, bh[j][1], bl[j][1]);
            }
            #pragma unroll
            for (int i = 0; i < MT; i++)
                #pragma unroll
                for (int j = 0; j < NT; j++) {
                    mma_bf16(acc[i][j], ah[i], bh[j]);
                    mma_bf16(acc[i][j], ah[i], bl[j]);
                    mma_bf16(acc[i][j], al[i], bh[j]);
                }
        }
    };

    // prologue: 2 stages in flight
    issue(0, 0); cp_commit();
    issue(1, 1); cp_commit();
    cp_wait<1>();
    __syncthreads();

    for (int kt = 0; kt < KT; kt++) {
        if (kt + 2 < KT) issue(kt + 2, (kt + 2) % 3);
        cp_commit();
        compute(kt % 3);
        cp_wait<1>();
        __syncthreads();
    }

    // epilogue
    auto epi = [&](float v, int rr, int cc) -> float {
        if (EPI == EPI_PHI) {
            return v > 0.f ? v + 1.f : expf(v);
        } else if (EPI == EPI_GELU) {
            v += bias[cc];
            float u = 0.7978845608028654f * (v + 0.044715f * v * v * v);
            return 0.5f * v * (1.f + tanhf(u));
        } else if (EPI == EPI_RES) {
            return v + bias[cc] + res[(size_t)rr * N + cc];
        }
        return v;
    };

    #pragma unroll
    for (int i = 0; i < MT; i++) {
        #pragma unroll
        for (int j = 0; j < NT; j++) {
            int rr = row0 + wm * WM + i * 16 + lr;
            int cc = col0 + wn * WN + j * 8 + 2 * lc;
            float2 o0, o1;
            o0.x = epi(acc[i][j][0], rr, cc);
            o0.y = epi(acc[i][j][1], rr, cc + 1);
            *(float2*)(C + (size_t)rr * N + cc) = o0;
            o1.x = epi(acc[i][j][2], rr + 8, cc);
            o1.y = epi(acc[i][j][3], rr + 8, cc + 1);
            *(float2*)(C + (size_t)(rr + 8) * N + cc) = o1;
        }
    }
}

// ---------------- kv = sum_s phi_k[s,p] * v[s,f]  (per batch) ----------------
__global__ void __launch_bounds__(256)
kv_kernel(const float* __restrict__ Kp, const float* __restrict__ V,
          float* __restrict__ KV)
{
    int b  = blockIdx.y;
    int f0 = blockIdx.x * 64;
    const float* Kb = Kp + (size_t)b * SS * PP;
    const float* Vb = V  + (size_t)b * SS * EE;

    __shared__ float Ks[32 * 64];
    __shared__ float Vs[32 * 64];
    int tid = threadIdx.x;
    int tx = tid % 16, ty = tid / 16;

    float acc[4][4];
    #pragma unroll
    for (int i = 0; i < 4; i++)
        #pragma unroll
        for (int j = 0; j < 4; j++) acc[i][j] = 0.f;

    for (int s0 = 0; s0 < SS; s0 += 32) {
        #pragma unroll
        for (int i = 0; i < 2; i++) {
            int idx = tid + i * 256;
            int r = idx / 16, c4 = idx % 16;
            *(float4*)(Ks + r * 64 + c4 * 4) =
                *(const float4*)(Kb + (size_t)(s0 + r) * PP + c4 * 4);
            *(float4*)(Vs + r * 64 + c4 * 4) =
                *(const float4*)(Vb + (size_t)(s0 + r) * EE + f0 + c4 * 4);
        }
        __syncthreads();
        #pragma unroll
        for (int k = 0; k < 32; k++) {
            float rp[4], rv[4];
            #pragma unroll
            for (int i = 0; i < 4; i++) rp[i] = Ks[k * 64 + ty * 4 + i];
            #pragma unroll
            for (int j = 0; j < 4; j++) rv[j] = Vs[k * 64 + tx * 4 + j];
            #pragma unroll
            for (int i = 0; i < 4; i++)
                #pragma unroll
                for (int j = 0; j < 4; j++)
                    acc[i][j] = fmaf(rp[i], rv[j], acc[i][j]);
        }
        __syncthreads();
    }
    #pragma unroll
    for (int i = 0; i < 4; i++)
        #pragma unroll
        for (int j = 0; j < 4; j++)
            KV[((size_t)b * PP + ty * 4 + i) * EE + f0 + tx * 4 + j] = acc[i][j];
}

// ---------------- z = sum_s phi_k[s,p] (per batch) ----------------
__global__ void z_kernel(const float* __restrict__ Kp, float* __restrict__ Z) {
    int b = blockIdx.x;
    int tid = threadIdx.x;
    int p = tid & 63, g = tid >> 6;
    const float* Kb = Kp + (size_t)b * SS * PP;
    float acc = 0.f;
    for (int s = g; s < SS; s += 4) acc += Kb[(size_t)s * PP + p];
    __shared__ float smem[256];
    smem[tid] = acc;
    __syncthreads();
    if (g == 0) Z[b * PP + p] = smem[p] + smem[64 + p] + smem[128 + p] + smem[192 + p];
}

// ---------------- attn = (phi_q @ KV) / (phi_q . z + eps) ----------------
__global__ void __launch_bounds__(256)
num_kernel(const float* __restrict__ Qp, const float* __restrict__ KV,
           const float* __restrict__ Z, float* __restrict__ OUT)
{
    int b  = blockIdx.z;
    int s0 = blockIdx.y * 64;
    int f0 = blockIdx.x * 128;

    __shared__ float Qs[64 * 64];
    __shared__ float KVs[64 * 128];
    __shared__ float Zs[64];

    int tid = threadIdx.x;
    const float* Qb = Qp + ((size_t)b * SS + s0) * PP;
    #pragma unroll
    for (int i = 0; i < 4; i++) {
        int idx = tid + i * 256;
        int r = idx / 16, c4 = idx % 16;
        *(float4*)(Qs + r * 64 + c4 * 4) =
            *(const float4*)(Qb + (size_t)r * PP + c4 * 4);
    }
    const float* KVb = KV + (size_t)b * PP * EE;
    #pragma unroll
    for (int i = 0; i < 8; i++) {
        int idx = tid + i * 256;
        int r = idx / 32, c4 = idx % 32;
        *(float4*)(KVs + r * 128 + c4 * 4) =
            *(const float4*)(KVb + (size_t)r * EE + f0 + c4 * 4);
    }
    if (tid < 64) Zs[tid] = Z[b * PP + tid];
    __syncthreads();

    int tx = tid % 16, ty = tid / 16;
    float acc[4][8];
    float den[4] = {0.f, 0.f, 0.f, 0.f};
    #pragma unroll
    for (int i = 0; i < 4; i++)
        #pragma unroll
        for (int j = 0; j < 8; j++) acc[i][j] = 0.f;

    #pragma unroll 8
    for (int k = 0; k < 64; k++) {
        float rq[4];
        #pragma unroll
        for (int i = 0; i < 4; i++) rq[i] = Qs[(ty * 4 + i) * 64 + k];
        float rz = Zs[k];
        #pragma unroll
        for (int i = 0; i < 4; i++) den[i] = fmaf(rq[i], rz, den[i]);
        #pragma unroll
        for (int j = 0; j < 8; j++) {
            float rk = KVs[k * 128 + tx * 8 + j];
            #pragma unroll
            for (int i = 0; i < 4; i++) acc[i][j] = fmaf(rq[i], rk, acc[i][j]);
        }
    }

    float* Ob = OUT + ((size_t)b * SS + s0) * EE;
    #pragma unroll
    for (int i = 0; i < 4; i++) {
        float inv = 1.f / (den[i] + 1e-6f);
        #pragma unroll
        for (int j = 0; j < 8; j++)
            Ob[(size_t)(ty * 4 + i) * EE + f0 + tx * 8 + j] = acc[i][j] * inv;
    }
}

// ---------------- layernorm (in place) ----------------
__global__ void ln_kernel(float* __restrict__ X,
                          const float* __restrict__ gam,
                          const float* __restrict__ bet) {
    int row = blockIdx.x;
    float* xr = X + (size_t)row * EE;
    int tid = threadIdx.x;
    float4 v = ((float4*)xr)[tid];
    float s = v.x + v.y + v.z + v.w;
    float q = v.x * v.x + v.y * v.y + v.z * v.z + v.w * v.w;
    #pragma unroll
    for (int o = 16; o; o >>= 1) {
        s += __shfl_xor_sync(0xffffffffu, s, o);
        q += __shfl_xor_sync(0xffffffffu, q, o);
    }
    __shared__ float ss[4], qq[4];
    int w = tid >> 5;
    if ((tid & 31) == 0) { ss[w] = s; qq[w] = q; }
    __syncthreads();
    s = ss[0] + ss[1] + ss[2] + ss[3];
    q = qq[0] + qq[1] + qq[2] + qq[3];
    float mu  = s * (1.f / EE);
    float var = q * (1.f / EE) - mu * mu;
    float inv = rsqrtf(var + 1e-5f);
    float4 g4 = ((const float4*)gam)[tid];
    float4 b4 = ((const float4*)bet)[tid];
    float4 o;
    o.x = (v.x - mu) * inv * g4.x + b4.x;
    o.y = (v.y - mu) * inv * g4.y + b4.y;
    o.z = (v.z - mu) * inv * g4.z + b4.z;
    o.w = (v.w - mu) * inv * g4.w + b4.w;
    ((float4*)xr)[tid] = o;
}

// ---------------- head ----------------
__global__ void head_kernel(const float* __restrict__ Hm,
                            const float* __restrict__ Wh1,
                            const float* __restrict__ bh1,
                            const float* __restrict__ Wh2,
                            const float* __restrict__ bh2,
                            float* __restrict__ out) {
    int b = blockIdx.x;
    int tid = threadIdx.x;
    const float* hr = Hm + (size_t)b * SS * EE;
    float acc = bh1[tid];
    for (int e = 0; e < EE; e++) acc = fmaf(hr[e], Wh1[e * HH + tid], acc);
    acc = fmaxf(acc, 0.f);
    __shared__ float hid[HH];
    hid[tid] = acc;
    __syncthreads();
    if (tid < CC) {
        float a = bh2[tid];
        for (int h = 0; h < HH; h++) a = fmaf(hid[h], Wh2[h * CC + tid], a);
        out[b * CC + tid] = a;
    }
}

// ---------------- launch ----------------
static size_t gemm_smem(int BM, int BN) {
    return (size_t)(3 * (BM * 40 + 32 * (BN + 4))) * 4;
}

extern "C" void kernel_launch(void* const* d_in, const int* in_sizes, int n_in,
                              void* d_out, int out_size) {
    const int*   x    = (const int*)  d_in[0];
    const float* emb  = (const float*)d_in[1];
    const float* pos  = (const float*)d_in[2];
    const float* Wq   = (const float*)d_in[3];
    const float* Wk   = (const float*)d_in[4];
    const float* Wv   = (const float*)d_in[5];
    const float* Wo   = (const float*)d_in[6];
    const float* ln_g = (const float*)d_in[7];
    const float* ln_b = (const float*)d_in[8];
    const float* W1   = (const float*)d_in[9];
    const float* b1   = (const float*)d_in[10];
    const float* W2   = (const float*)d_in[11];
    const float* b2   = (const float*)d_in[12];
    const float* Wh1  = (const float*)d_in[13];
    const float* bh1  = (const float*)d_in[14];
    const float* Wh2  = (const float*)d_in[15];
    const float* bh2  = (const float*)d_in[16];
    float* out = (float*)d_out;

    float *H, *A, *V, *NUM, *Mb, *Q, *Kq, *KV, *Z;
    cudaGetSymbolAddress((void**)&H,   g_H);
    cudaGetSymbolAddress((void**)&A,   g_A);
    cudaGetSymbolAddress((void**)&V,   g_V);
    cudaGetSymbolAddress((void**)&NUM, g_NUM);
    cudaGetSymbolAddress((void**)&Mb,  g_M);
    cudaGetSymbolAddress((void**)&Q,   g_Q);
    cudaGetSymbolAddress((void**)&Kq,  g_K);
    cudaGetSymbolAddress((void**)&KV,  g_KV);
    cudaGetSymbolAddress((void**)&Z,   g_Z);

    const size_t sm64  = gemm_smem(128, 64);
    const size_t sm128 = gemm_smem(128, 128);
    cudaFuncSetAttribute(gemm_b16x2<128, 64, 32, 32, EPI_PHI>,
                         cudaFuncAttributeMaxDynamicSharedMemorySize, (int)sm64);
    cudaFuncSetAttribute(gemm_b16x2<128, 128, 64, 32, EPI_NONE>,
                         cudaFuncAttributeMaxDynamicSharedMemorySize, (int)sm128);
    cudaFuncSetAttribute(gemm_b16x2<128, 128, 64, 32, EPI_GELU>,
                         cudaFuncAttributeMaxDynamicSharedMemorySize, (int)sm128);
    cudaFuncSetAttribute(gemm_b16x2<128, 128, 64, 32, EPI_RES>,
                         cudaFuncAttributeMaxDynamicSharedMemorySize, (int)sm128);

    embed_kernel<<<MROWS, 128>>>(x, emb, pos, H);

    for (int l = 0; l < LL; l++) {
        const float* Wql = Wq + (size_t)l * EE * PP;
        const float* Wkl = Wk + (size_t)l * EE * PP;
        const float* Wvl = Wv + (size_t)l * EE * EE;
        const float* Wol = Wo + (size_t)l * EE * EE;
        const float* W1l = W1 + (size_t)l * EE * FF;
        const float* W2l = W2 + (size_t)l * FF * EE;

        gemm_b16x2<128, 64, 32, 32, EPI_PHI>
            <<<dim3(PP / 64, MROWS / 128), 256, sm64>>>(
                MROWS, PP, EE, H, Wql, nullptr, nullptr, Q);
        gemm_b16x2<128, 64, 32, 32, EPI_PHI>
            <<<dim3(PP / 64, MROWS / 128), 256, sm64>>>(
                MROWS, PP, EE, H, Wkl, nullptr, nullptr, Kq);
        gemm_b16x2<128, 128, 64, 32, EPI_NONE>
            <<<dim3(EE / 128, MROWS / 128), 256, sm128>>>(
                MROWS, EE, EE, H, Wvl, nullptr, nullptr, V);

        kv_kernel<<<dim3(EE / 64, BB), 256>>>(Kq, V, KV);
        z_kernel<<<BB, 256>>>(Kq, Z);
        num_kernel<<<dim3(EE / 128, SS / 64, BB), 256>>>(Q, KV, Z, NUM);

        gemm_b16x2<128, 128, 64, 32, EPI_NONE>
            <<<dim3(EE / 128, MROWS / 128), 256, sm128>>>(
                MROWS, EE, EE, NUM, Wol, nullptr, nullptr, A);

        ln_kernel<<<MROWS, 128>>>(A, ln_g + (size_t)l * EE, ln_b + (size_t)l * EE);

        gemm_b16x2<128, 128, 64, 32, EPI_GELU>
            <<<dim3(FF / 128, MROWS / 128), 256, sm128>>>(
                MROWS, FF, EE, A, W1l, b1 + (size_t)l * FF, nullptr, Mb);
        gemm_b16x2<128, 128, 64, 32, EPI_RES>
            <<<dim3(EE / 128, MROWS / 128), 256, sm128>>>(
                MROWS, EE, FF, Mb, W2l, b2 + (size_t)l * EE, H, H);
    }

    head_kernel<<<BB, HH>>>(H, Wh1, bh1, Wh2, bh2, out);
}

// round 4
// speedup vs baseline: 2.3365x; 1.0441x over previous
#include <cuda_runtime.h>
#include <math.h>

// Problem constants
#define BB   8
#define SS   4096
#define EE   512
#define PP   64
#define LL   4
#define HH   256
#define CC   2
#define FF   2048               // 4*E
#define MROWS (BB*SS)           // 32768
#define NSPLIT 8                // S-splits for kv/z

enum { EPI_NONE = 0, EPI_PHI = 1, EPI_GELU = 2, EPI_RES = 3 };

// ---------------- scratch (device globals; allocation-free) ----------------
__device__ float g_H  [(size_t)MROWS*EE];     // hidden / residual (fp32)
__device__ float g_A  [(size_t)MROWS*EE];     // Wo output -> ln input
__device__ float g_V  [(size_t)MROWS*EE];
__device__ float g_Q  [(size_t)MROWS*PP];
__device__ float g_K  [(size_t)MROWS*PP];
__device__ float g_KV [(size_t)BB*PP*EE];
__device__ float g_KVp[(size_t)NSPLIT*BB*PP*EE];
__device__ float g_Z  [(size_t)BB*PP];
__device__ float g_Zp [(size_t)NSPLIT*BB*PP];

// packed bf16x2 (along k) operand arrays: word = (bf16(k even) | bf16(k odd)<<16)
__device__ unsigned g_Hh [(size_t)MROWS*(EE/2)],  g_Hl [(size_t)MROWS*(EE/2)];
__device__ unsigned g_NMh[(size_t)MROWS*(EE/2)],  g_NMl[(size_t)MROWS*(EE/2)];
__device__ unsigned g_LNh[(size_t)MROWS*(EE/2)],  g_LNl[(size_t)MROWS*(EE/2)];
__device__ unsigned g_Mbh[(size_t)MROWS*(FF/2)],  g_Mbl[(size_t)MROWS*(FF/2)];
// pre-split transposed weights [N][K/2]
__device__ unsigned g_Wqh[(size_t)LL*PP*(EE/2)],  g_Wql_[(size_t)LL*PP*(EE/2)];
__device__ unsigned g_Wkh[(size_t)LL*PP*(EE/2)],  g_Wkl_[(size_t)LL*PP*(EE/2)];
__device__ unsigned g_Wvh[(size_t)LL*EE*(EE/2)],  g_Wvl_[(size_t)LL*EE*(EE/2)];
__device__ unsigned g_Woh[(size_t)LL*EE*(EE/2)],  g_Wol_[(size_t)LL*EE*(EE/2)];
__device__ unsigned g_W1h[(size_t)LL*FF*(EE/2)],  g_W1l_[(size_t)LL*FF*(EE/2)];
__device__ unsigned g_W2h[(size_t)LL*EE*(FF/2)],  g_W2l_[(size_t)LL*EE*(FF/2)];

// ---------------- helpers ----------------
__device__ __forceinline__ void cp_async16(void* smem, const void* gmem) {
    unsigned sa = (unsigned)__cvta_generic_to_shared(smem);
    asm volatile("cp.async.cg.shared.global [%0], [%1], 16;" :: "r"(sa), "l"(gmem));
}
__device__ __forceinline__ void cp_commit() {
    asm volatile("cp.async.commit_group;");
}
template<int N>
__device__ __forceinline__ void cp_wait() {
    asm volatile("cp.async.wait_group %0;" :: "n"(N));
}

// Split two consecutive fp32 into packed bf16x2 hi and lo. low16 = first elem.
__device__ __forceinline__ void split2(float x, float y, unsigned& hi, unsigned& lo) {
    asm("cvt.rn.bf16x2.f32 %0, %1, %2;" : "=r"(hi) : "f"(y), "f"(x));
    float hx = __uint_as_float(hi << 16);
    float hy = __uint_as_float(hi & 0xFFFF0000u);
    float lx = x - hx;
    float ly = y - hy;
    asm("cvt.rn.bf16x2.f32 %0, %1, %2;" : "=r"(lo) : "f"(ly), "f"(lx));
}

__device__ __forceinline__ void mma_bf16(float c[4], const unsigned a[4], const unsigned b[2]) {
    asm volatile(
        "mma.sync.aligned.m16n8k16.row.col.f32.bf16.bf16.f32 "
        "{%0,%1,%2,%3}, {%4,%5,%6,%7}, {%8,%9}, {%0,%1,%2,%3};"
        : "+f"(c[0]), "+f"(c[1]), "+f"(c[2]), "+f"(c[3])
        : "r"(a[0]), "r"(a[1]), "r"(a[2]), "r"(a[3]), "r"(b[0]), "r"(b[1]));
}

// ---------------- weight transpose + split: W[K][N] -> T[N][K/2] words ----------------
__global__ void wsplit_kernel(const float* __restrict__ W,
                              unsigned* __restrict__ Th, unsigned* __restrict__ Tl,
                              int K, int N) {
    const float* Wl = W + (size_t)blockIdx.z * K * N;
    unsigned* Thl = Th + (size_t)blockIdx.z * N * (K >> 1);
    unsigned* Tll = Tl + (size_t)blockIdx.z * N * (K >> 1);
    __shared__ float t[32][33];
    int k0 = blockIdx.y * 32, n0 = blockIdx.x * 32;
    int tx = threadIdx.x, ty = threadIdx.y;     // 32 x 8
    #pragma unroll
    for (int i = 0; i < 4; i++)
        t[ty + i * 8][tx] = Wl[(size_t)(k0 + ty + i * 8) * N + n0 + tx];
    __syncthreads();
    int tid = ty * 32 + tx;
    #pragma unroll
    for (int i = 0; i < 2; i++) {
        int w = tid + i * 256;
        int n = w >> 4, kp = w & 15;
        unsigned h, l;
        split2(t[2 * kp][n], t[2 * kp + 1][n], h, l);
        size_t o = (size_t)(n0 + n) * (K >> 1) + (k0 >> 1) + kp;
        Thl[o] = h;
        Tll[o] = l;
    }
}

// ---------------- embedding + positional (fp32 + packed) ----------------
__global__ void embed_kernel(const int* __restrict__ x,
                             const float* __restrict__ emb,
                             const float* __restrict__ pos,
                             float* __restrict__ H,
                             unsigned* __restrict__ Hh, unsigned* __restrict__ Hl) {
    int row = blockIdx.x;
    int s   = row & (SS - 1);
    int tok = x[row];
    const float4* e4 = (const float4*)(emb + (size_t)tok * EE);
    const float4* p4 = (const float4*)(pos + (size_t)s * EE);
    int t = threadIdx.x;                    // 128, 4 elems each
    float4 a = e4[t], b = p4[t];
    float4 o = make_float4(a.x + b.x, a.y + b.y, a.z + b.z, a.w + b.w);
    ((float4*)(H + (size_t)row * EE))[t] = o;
    unsigned h0, l0, h1, l1;
    split2(o.x, o.y, h0, l0);
    split2(o.z, o.w, h1, l1);
    size_t wo = (size_t)row * (EE / 2) + 2 * t;
    Hh[wo] = h0; Hh[wo + 1] = h1;
    Hl[wo] = l0; Hl[wo + 1] = l1;
}

// ---------------- packed-operand bf16x2 tensor-core GEMM ----------------
// C[M,N] = A[M,K] @ B[K,N]. A given as packed hi/lo [M][K/2] words;
// B given as packed transposed hi/lo [N][K/2] words. BK=32, 3-stage cp.async.
template<int BM, int BN, int WM, int WN, int EPI, bool WF32, bool WPACK>
__global__ void __launch_bounds__((BM/WM)*(BN/WN)*32)
gemm_pk(int M, int N, int K,
        const unsigned* __restrict__ Ah, const unsigned* __restrict__ Al,
        const unsigned* __restrict__ Bh, const unsigned* __restrict__ Bl,
        const float* __restrict__ bias,
        const float* __restrict__ res,
        float* __restrict__ C,
        unsigned* __restrict__ Ch, unsigned* __restrict__ Cl)
{
    constexpr int WARPS_M = BM / WM;
    constexpr int WARPS_N = BN / WN;
    constexpr int NTH = WARPS_M * WARPS_N * 32;
    constexpr int LDW = 20;            // 16 words + 4 pad per row
    constexpr int ASZ = BM * LDW;
    constexpr int BSZ = BN * LDW;
    constexpr int MT = WM / 16;
    constexpr int NT = WN / 8;
    constexpr int A_CNT = BM * 4 / NTH;   // 16B chunks per stage per array
    constexpr int B_CNT = BN * 4 / NTH;

    extern __shared__ unsigned smw[];
    unsigned* Ash = smw;
    unsigned* Asl = smw + 3 * ASZ;
    unsigned* Bsh = smw + 6 * ASZ;
    unsigned* Bsl = smw + 6 * ASZ + 3 * BSZ;

    const int tid  = threadIdx.x;
    const int lane = tid & 31;
    const int warp = tid >> 5;
    const int wm   = warp / WARPS_N;
    const int wn   = warp % WARPS_N;
    const int lr   = lane >> 2;
    const int lc   = lane & 3;
    const int row0 = blockIdx.y * BM;
    const int col0 = blockIdx.x * BN;
    const int KW   = K >> 1;
    const int KT   = K / 32;

    float acc[MT][NT][4];
    #pragma unroll
    for (int i = 0; i < MT; i++)
        #pragma unroll
        for (int j = 0; j < NT; j++)
            #pragma unroll
            for (int q = 0; q < 4; q++) acc[i][j][q] = 0.f;

    auto issue = [&](int kt, int st) {
        int goff = kt * 16;
        #pragma unroll
        for (int i = 0; i < A_CNT; i++) {
            int idx = tid + i * NTH;
            int r = idx >> 2, c = (idx & 3) * 4;
            size_t g = (size_t)(row0 + r) * KW + goff + c;
            cp_async16(Ash + st * ASZ + r * LDW + c, Ah + g);
            cp_async16(Asl + st * ASZ + r * LDW + c, Al + g);
        }
        #pragma unroll
        for (int i = 0; i < B_CNT; i++) {
            int idx = tid + i * NTH;
            int r = idx >> 2, c = (idx & 3) * 4;
            size_t g = (size_t)(col0 + r) * KW + goff + c;
            cp_async16(Bsh + st * BSZ + r * LDW + c, Bh + g);
            cp_async16(Bsl + st * BSZ + r * LDW + c, Bl + g);
        }
    };

    auto compute = [&](int st) {
        const unsigned* Ah_ = Ash + st * ASZ;
        const unsigned* Al_ = Asl + st * ASZ;
        const unsigned* Bh_ = Bsh + st * BSZ;
        const unsigned* Bl_ = Bsl + st * BSZ;
        #pragma unroll
        for (int kk = 0; kk < 2; kk++) {
            unsigned ah[MT][4], al[MT][4], bh[NT][2], bl[NT][2];
            #pragma unroll
            for (int i = 0; i < MT; i++) {
                int base = (wm * WM + i * 16 + lr) * LDW + kk * 8 + lc;
                ah[i][0] = Ah_[base];           al[i][0] = Al_[base];
                ah[i][1] = Ah_[base + 8 * LDW]; al[i][1] = Al_[base + 8 * LDW];
                ah[i][2] = Ah_[base + 4];       al[i][2] = Al_[base + 4];
                ah[i][3] = Ah_[base + 8 * LDW + 4]; al[i][3] = Al_[base + 8 * LDW + 4];
            }
            #pragma unroll
            for (int j = 0; j < NT; j++) {
                int bbase = (wn * WN + j * 8 + lr) * LDW + kk * 8 + lc;
                bh[j][0] = Bh_[bbase];     bl[j][0] = Bl_[bbase];
                bh[j][1] = Bh_[bbase + 4]; bl[j][1] = Bl_[bbase + 4];
            }
            #pragma unroll
            for (int i = 0; i < MT; i++)
                #pragma unroll
                for (int j = 0; j < NT; j++) {
                    mma_bf16(acc[i][j], ah[i], bh[j]);
                    mma_bf16(acc[i][j], ah[i], bl[j]);
                    mma_bf16(acc[i][j], al[i], bh[j]);
                }
        }
    };

    issue(0, 0); cp_commit();
    issue(1, 1); cp_commit();
    cp_wait<1>();
    __syncthreads();

    for (int kt = 0; kt < KT; kt++) {
        if (kt + 2 < KT) issue(kt + 2, (kt + 2) % 3);
        cp_commit();
        compute(kt % 3);
        cp_wait<1>();
        __syncthreads();
    }

    auto epi = [&](float v, int rr, int cc) -> float {
        if (EPI == EPI_PHI) {
            return v > 0.f ? v + 1.f : expf(v);
        } else if (EPI == EPI_GELU) {
            v += bias[cc];
            float u = 0.7978845608028654f * (v + 0.044715f * v * v * v);
            return 0.5f * v * (1.f + tanhf(u));
        } else if (EPI == EPI_RES) {
            return v + bias[cc] + res[(size_t)rr * N + cc];
        }
        return v;
    };

    #pragma unroll
    for (int i = 0; i < MT; i++) {
        #pragma unroll
        for (int j = 0; j < NT; j++) {
            int rr = row0 + wm * WM + i * 16 + lr;
            int cc = col0 + wn * WN + j * 8 + 2 * lc;
            float e00 = epi(acc[i][j][0], rr, cc);
            float e01 = epi(acc[i][j][1], rr, cc + 1);
            float e10 = epi(acc[i][j][2], rr + 8, cc);
            float e11 = epi(acc[i][j][3], rr + 8, cc + 1);
            if (WF32) {
                *(float2*)(C + (size_t)rr * N + cc)       = make_float2(e00, e01);
                *(float2*)(C + (size_t)(rr + 8) * N + cc) = make_float2(e10, e11);
            }
            if (WPACK) {
                unsigned h, l;
                split2(e00, e01, h, l);
                size_t w0 = (size_t)rr * (N >> 1) + (cc >> 1);
                Ch[w0] = h; Cl[w0] = l;
                split2(e10, e11, h, l);
                size_t w1 = (size_t)(rr + 8) * (N >> 1) + (cc >> 1);
                Ch[w1] = h; Cl[w1] = l;
            }
        }
    }
}

// ---------------- kv partials: split over S ----------------
// grid (E/64, B, NSPLIT)
__global__ void __launch_bounds__(256)
kv_kernel(const float* __restrict__ Kp, const float* __restrict__ V,
          float* __restrict__ KVp)
{
    int b  = blockIdx.y;
    int f0 = blockIdx.x * 64;
    int sp = blockIdx.z;
    const float* Kb = Kp + (size_t)b * SS * PP;
    const float* Vb = V  + (size_t)b * SS * EE;

    __shared__ float Ks[32 * 64];
    __shared__ float Vs[32 * 64];
    int tid = threadIdx.x;
    int tx = tid % 16, ty = tid / 16;

    float acc[4][4];
    #pragma unroll
    for (int i = 0; i < 4; i++)
        #pragma unroll
        for (int j = 0; j < 4; j++) acc[i][j] = 0.f;

    int sbeg = sp * (SS / NSPLIT), send = sbeg + (SS / NSPLIT);
    for (int s0 = sbeg; s0 < send; s0 += 32) {
        #pragma unroll
        for (int i = 0; i < 2; i++) {
            int idx = tid + i * 256;
            int r = idx / 16, c4 = idx % 16;
            *(float4*)(Ks + r * 64 + c4 * 4) =
                *(const float4*)(Kb + (size_t)(s0 + r) * PP + c4 * 4);
            *(float4*)(Vs + r * 64 + c4 * 4) =
                *(const float4*)(Vb + (size_t)(s0 + r) * EE + f0 + c4 * 4);
        }
        __syncthreads();
        #pragma unroll
        for (int k = 0; k < 32; k++) {
            float rp[4], rv[4];
            #pragma unroll
            for (int i = 0; i < 4; i++) rp[i] = Ks[k * 64 + ty * 4 + i];
            #pragma unroll
            for (int j = 0; j < 4; j++) rv[j] = Vs[k * 64 + tx * 4 + j];
            #pragma unroll
            for (int i = 0; i < 4; i++)
                #pragma unroll
                for (int j = 0; j < 4; j++)
                    acc[i][j] = fmaf(rp[i], rv[j], acc[i][j]);
        }
        __syncthreads();
    }
    float* out = KVp + (size_t)sp * BB * PP * EE;
    #pragma unroll
    for (int i = 0; i < 4; i++)
        #pragma unroll
        for (int j = 0; j < 4; j++)
            out[((size_t)b * PP + ty * 4 + i) * EE + f0 + tx * 4 + j] = acc[i][j];
}

__global__ void reduce_kv(const float* __restrict__ KVp, float* __restrict__ KV) {
    size_t idx = (size_t)blockIdx.x * 256 + threadIdx.x;   // over B*P*E
    float s = 0.f;
    #pragma unroll
    for (int sp = 0; sp < NSPLIT; sp++)
        s += KVp[(size_t)sp * BB * PP * EE + idx];
    KV[idx] = s;
}

// ---------------- z partials ----------------
// grid (B, NSPLIT)
__global__ void z_kernel(const float* __restrict__ Kp, float* __restrict__ Zp) {
    int b = blockIdx.x, sp = blockIdx.y;
    int tid = threadIdx.x;
    int p = tid & 63, g = tid >> 6;
    const float* Kb = Kp + (size_t)b * SS * PP;
    float acc = 0.f;
    int sbeg = sp * (SS / NSPLIT), send = sbeg + (SS / NSPLIT);
    for (int s = sbeg + g; s < send; s += 4) acc += Kb[(size_t)s * PP + p];
    __shared__ float smem[256];
    smem[tid] = acc;
    __syncthreads();
    if (g == 0)
        Zp[(size_t)sp * BB * PP + b * PP + p] =
            smem[p] + smem[64 + p] + smem[128 + p] + smem[192 + p];
}

__global__ void reduce_z(const float* __restrict__ Zp, float* __restrict__ Z) {
    int idx = blockIdx.x * 256 + threadIdx.x;
    if (idx < BB * PP) {
        float s = 0.f;
        #pragma unroll
        for (int sp = 0; sp < NSPLIT; sp++) s += Zp[sp * BB * PP + idx];
        Z[idx] = s;
    }
}

// ---------------- attn = (phi_q @ KV) / (phi_q . z + eps), packed output ----------------
__global__ void __launch_bounds__(256)
num_kernel(const float* __restrict__ Qp, const float* __restrict__ KV,
           const float* __restrict__ Z,
           unsigned* __restrict__ Oh, unsigned* __restrict__ Ol)
{
    int b  = blockIdx.z;
    int s0 = blockIdx.y * 64;
    int f0 = blockIdx.x * 128;

    __shared__ float Qs[64 * 64];
    __shared__ float KVs[64 * 128];
    __shared__ float Zs[64];

    int tid = threadIdx.x;
    const float* Qb = Qp + ((size_t)b * SS + s0) * PP;
    #pragma unroll
    for (int i = 0; i < 4; i++) {
        int idx = tid + i * 256;
        int r = idx / 16, c4 = idx % 16;
        *(float4*)(Qs + r * 64 + c4 * 4) =
            *(const float4*)(Qb + (size_t)r * PP + c4 * 4);
    }
    const float* KVb = KV + (size_t)b * PP * EE;
    #pragma unroll
    for (int i = 0; i < 8; i++) {
        int idx = tid + i * 256;
        int r = idx / 32, c4 = idx % 32;
        *(float4*)(KVs + r * 128 + c4 * 4) =
            *(const float4*)(KVb + (size_t)r * EE + f0 + c4 * 4);
    }
    if (tid < 64) Zs[tid] = Z[b * PP + tid];
    __syncthreads();

    int tx = tid % 16, ty = tid / 16;
    float acc[4][8];
    float den[4] = {0.f, 0.f, 0.f, 0.f};
    #pragma unroll
    for (int i = 0; i < 4; i++)
        #pragma unroll
        for (int j = 0; j < 8; j++) acc[i][j] = 0.f;

    #pragma unroll 8
    for (int k = 0; k < 64; k++) {
        float rq[4];
        #pragma unroll
        for (int i = 0; i < 4; i++) rq[i] = Qs[(ty * 4 + i) * 64 + k];
        float rz = Zs[k];
        #pragma unroll
        for (int i = 0; i < 4; i++) den[i] = fmaf(rq[i], rz, den[i]);
        #pragma unroll
        for (int j = 0; j < 8; j++) {
            float rk = KVs[k * 128 + tx * 8 + j];
            #pragma unroll
            for (int i = 0; i < 4; i++) acc[i][j] = fmaf(rq[i], rk, acc[i][j]);
        }
    }

    #pragma unroll
    for (int i = 0; i < 4; i++) {
        float inv = 1.f / (den[i] + 1e-6f);
        size_t row = (size_t)b * SS + s0 + ty * 4 + i;
        size_t wbase = row * (EE / 2) + f0 / 2 + tx * 4;
        #pragma unroll
        for (int jw = 0; jw < 4; jw++) {
            unsigned h, l;
            split2(acc[i][2 * jw] * inv, acc[i][2 * jw + 1] * inv, h, l);
            Oh[wbase + jw] = h;
            Ol[wbase + jw] = l;
        }
    }
}

// ---------------- layernorm: read fp32, write packed ----------------
__global__ void ln_kernel(const float* __restrict__ X,
                          const float* __restrict__ gam,
                          const float* __restrict__ bet,
                          unsigned* __restrict__ Oh, unsigned* __restrict__ Ol) {
    int row = blockIdx.x;
    const float* xr = X + (size_t)row * EE;
    int tid = threadIdx.x;                 // 128
    float4 v = ((const float4*)xr)[tid];
    float s = v.x + v.y + v.z + v.w;
    float q = v.x * v.x + v.y * v.y + v.z * v.z + v.w * v.w;
    #pragma unroll
    for (int o = 16; o; o >>= 1) {
        s += __shfl_xor_sync(0xffffffffu, s, o);
        q += __shfl_xor_sync(0xffffffffu, q, o);
    }
    __shared__ float ss[4], qq[4];
    int w = tid >> 5;
    if ((tid & 31) == 0) { ss[w] = s; qq[w] = q; }
    __syncthreads();
    s = ss[0] + ss[1] + ss[2] + ss[3];
    q = qq[0] + qq[1] + qq[2] + qq[3];
    float mu  = s * (1.f / EE);
    float var = q * (1.f / EE) - mu * mu;
    float inv = rsqrtf(var + 1e-5f);
    float4 g4 = ((const float4*)gam)[tid];
    float4 b4 = ((const float4*)bet)[tid];
    float o0 = (v.x - mu) * inv * g4.x + b4.x;
    float o1 = (v.y - mu) * inv * g4.y + b4.y;
    float o2 = (v.z - mu) * inv * g4.z + b4.z;
    float o3 = (v.w - mu) * inv * g4.w + b4.w;
    unsigned h0, l0, h1, l1;
    split2(o0, o1, h0, l0);
    split2(o2, o3, h1, l1);
    size_t wo = (size_t)row * (EE / 2) + 2 * tid;
    Oh[wo] = h0; Oh[wo + 1] = h1;
    Ol[wo] = l0; Ol[wo + 1] = l1;
}

// ---------------- head ----------------
__global__ void head_kernel(const float* __restrict__ Hm,
                            const float* __restrict__ Wh1,
                            const float* __restrict__ bh1,
                            const float* __restrict__ Wh2,
                            const float* __restrict__ bh2,
                            float* __restrict__ out) {
    int b = blockIdx.x;
    int tid = threadIdx.x;
    const float* hr = Hm + (size_t)b * SS * EE;
    float acc = bh1[tid];
    for (int e = 0; e < EE; e++) acc = fmaf(hr[e], Wh1[e * HH + tid], acc);
    acc = fmaxf(acc, 0.f);
    __shared__ float hid[HH];
    hid[tid] = acc;
    __syncthreads();
    if (tid < CC) {
        float a = bh2[tid];
        for (int h = 0; h < HH; h++) a = fmaf(hid[h], Wh2[h * CC + tid], a);
        out[b * CC + tid] = a;
    }
}

// ---------------- launch ----------------
static size_t gemm_smem(int BM, int BN) {
    return (size_t)(3 * (BM * 20 * 2 + BN * 20 * 2)) * 4;
}

extern "C" void kernel_launch(void* const* d_in, const int* in_sizes, int n_in,
                              void* d_out, int out_size) {
    const int*   x    = (const int*)  d_in[0];
    const float* emb  = (const float*)d_in[1];
    const float* pos  = (const float*)d_in[2];
    const float* Wq   = (const float*)d_in[3];
    const float* Wk   = (const float*)d_in[4];
    const float* Wv   = (const float*)d_in[5];
    const float* Wo   = (const float*)d_in[6];
    const float* ln_g = (const float*)d_in[7];
    const float* ln_b = (const float*)d_in[8];
    const float* W1   = (const float*)d_in[9];
    const float* b1   = (const float*)d_in[10];
    const float* W2   = (const float*)d_in[11];
    const float* b2   = (const float*)d_in[12];
    const float* Wh1  = (const float*)d_in[13];
    const float* bh1  = (const float*)d_in[14];
    const float* Wh2  = (const float*)d_in[15];
    const float* bh2  = (const float*)d_in[16];
    float* out = (float*)d_out;

    float *H, *A, *V, *Q, *Kq, *KV, *KVp, *Z, *Zp;
    cudaGetSymbolAddress((void**)&H,   g_H);
    cudaGetSymbolAddress((void**)&A,   g_A);
    cudaGetSymbolAddress((void**)&V,   g_V);
    cudaGetSymbolAddress((void**)&Q,   g_Q);
    cudaGetSymbolAddress((void**)&Kq,  g_K);
    cudaGetSymbolAddress((void**)&KV,  g_KV);
    cudaGetSymbolAddress((void**)&KVp, g_KVp);
    cudaGetSymbolAddress((void**)&Z,   g_Z);
    cudaGetSymbolAddress((void**)&Zp,  g_Zp);

    unsigned *Hh, *Hl, *NMh, *NMl, *LNh, *LNl, *Mbh, *Mbl;
    cudaGetSymbolAddress((void**)&Hh,  g_Hh);  cudaGetSymbolAddress((void**)&Hl,  g_Hl);
    cudaGetSymbolAddress((void**)&NMh, g_NMh); cudaGetSymbolAddress((void**)&NMl, g_NMl);
    cudaGetSymbolAddress((void**)&LNh, g_LNh); cudaGetSymbolAddress((void**)&LNl, g_LNl);
    cudaGetSymbolAddress((void**)&Mbh, g_Mbh); cudaGetSymbolAddress((void**)&Mbl, g_Mbl);

    unsigned *Wqh, *Wql, *Wkh, *Wkl, *Wvh, *Wvl, *Woh, *Wol, *W1h, *W1l, *W2h, *W2l;
    cudaGetSymbolAddress((void**)&Wqh, g_Wqh); cudaGetSymbolAddress((void**)&Wql, g_Wql_);
    cudaGetSymbolAddress((void**)&Wkh, g_Wkh); cudaGetSymbolAddress((void**)&Wkl, g_Wkl_);
    cudaGetSymbolAddress((void**)&Wvh, g_Wvh); cudaGetSymbolAddress((void**)&Wvl, g_Wvl_);
    cudaGetSymbolAddress((void**)&Woh, g_Woh); cudaGetSymbolAddress((void**)&Wol, g_Wol_);
    cudaGetSymbolAddress((void**)&W1h, g_W1h); cudaGetSymbolAddress((void**)&W1l, g_W1l_);
    cudaGetSymbolAddress((void**)&W2h, g_W2h); cudaGetSymbolAddress((void**)&W2l, g_W2l_);

    const size_t sm64  = gemm_smem(128, 64);
    const size_t sm128 = gemm_smem(128, 128);
    cudaFuncSetAttribute(gemm_pk<128, 64, 32, 32, EPI_PHI, true, false>,
                         cudaFuncAttributeMaxDynamicSharedMemorySize, (int)sm64);
    cudaFuncSetAttribute(gemm_pk<128, 128, 64, 32, EPI_NONE, true, false>,
                         cudaFuncAttributeMaxDynamicSharedMemorySize, (int)sm128);
    cudaFuncSetAttribute(gemm_pk<128, 128, 64, 32, EPI_GELU, false, true>,
                         cudaFuncAttributeMaxDynamicSharedMemorySize, (int)sm128);
    cudaFuncSetAttribute(gemm_pk<128, 128, 64, 32, EPI_RES, true, true>,
                         cudaFuncAttributeMaxDynamicSharedMemorySize, (int)sm128);

    // one-time weight transpose+split (all layers)
    dim3 wt(32, 8);
    wsplit_kernel<<<dim3(PP / 32, EE / 32, LL), wt>>>(Wq, Wqh, Wql, EE, PP);
    wsplit_kernel<<<dim3(PP / 32, EE / 32, LL), wt>>>(Wk, Wkh, Wkl, EE, PP);
    wsplit_kernel<<<dim3(EE / 32, EE / 32, LL), wt>>>(Wv, Wvh, Wvl, EE, EE);
    wsplit_kernel<<<dim3(EE / 32, EE / 32, LL), wt>>>(Wo, Woh, Wol, EE, EE);
    wsplit_kernel<<<dim3(FF / 32, EE / 32, LL), wt>>>(W1, W1h, W1l, EE, FF);
    wsplit_kernel<<<dim3(EE / 32, FF / 32, LL), wt>>>(W2, W2h, W2l, FF, EE);

    embed_kernel<<<MROWS, 128>>>(x, emb, pos, H, Hh, Hl);

    for (int l = 0; l < LL; l++) {
        size_t oQK = (size_t)l * PP * (EE / 2);
        size_t oV  = (size_t)l * EE * (EE / 2);
        size_t oW1 = (size_t)l * FF * (EE / 2);
        size_t oW2 = (size_t)l * EE * (FF / 2);

        gemm_pk<128, 64, 32, 32, EPI_PHI, true, false>
            <<<dim3(PP / 64, MROWS / 128), 256, sm64>>>(
                MROWS, PP, EE, Hh, Hl, Wqh + oQK, Wql + oQK,
                nullptr, nullptr, Q, nullptr, nullptr);
        gemm_pk<128, 64, 32, 32, EPI_PHI, true, false>
            <<<dim3(PP / 64, MROWS / 128), 256, sm64>>>(
                MROWS, PP, EE, Hh, Hl, Wkh + oQK, Wkl + oQK,
                nullptr, nullptr, Kq, nullptr, nullptr);
        gemm_pk<128, 128, 64, 32, EPI_NONE, true, false>
            <<<dim3(EE / 128, MROWS / 128), 256, sm128>>>(
                MROWS, EE, EE, Hh, Hl, Wvh + oV, Wvl + oV,
                nullptr, nullptr, V, nullptr, nullptr);

        kv_kernel<<<dim3(EE / 64, BB, NSPLIT), 256>>>(Kq, V, KVp);
        z_kernel<<<dim3(BB, NSPLIT), 256>>>(Kq, Zp);
        reduce_kv<<<(BB * PP * EE) / 256, 256>>>(KVp, KV);
        reduce_z<<<2, 256>>>(Zp, Z);
        num_kernel<<<dim3(EE / 128, SS / 64, BB), 256>>>(Q, KV, Z, NMh, NMl);

        gemm_pk<128, 128, 64, 32, EPI_NONE, true, false>
            <<<dim3(EE / 128, MROWS / 128), 256, sm128>>>(
                MROWS, EE, EE, NMh, NMl, Woh + oV, Wol + oV,
                nullptr, nullptr, A, nullptr, nullptr);

        ln_kernel<<<MROWS, 128>>>(A, ln_g + (size_t)l * EE, ln_b + (size_t)l * EE,
                                  LNh, LNl);

        gemm_pk<128, 128, 64, 32, EPI_GELU, false, true>
            <<<dim3(FF / 128, MROWS / 128), 256, sm128>>>(
                MROWS, FF, EE, LNh, LNl, W1h + oW1, W1l + oW1,
                b1 + (size_t)l * FF, nullptr, nullptr, Mbh, Mbl);
        gemm_pk<128, 128, 64, 32, EPI_RES, true, true>
            <<<dim3(EE / 128, MROWS / 128), 256, sm128>>>(
                MROWS, EE, FF, Mbh, Mbl, W2h + oW2, W2l + oW2,
                b2 + (size_t)l * EE, H, H, Hh, Hl);
    }

    head_kernel<<<BB, HH>>>(H, Wh1, bh1, Wh2, bh2, out);
}

// round 6
// speedup vs baseline: 2.3516x; 1.0065x over previous
#include <cuda_runtime.h>
#include <math.h>

// Problem constants
#define BB   8
#define SS   4096
#define EE   512
#define PP   64
#define LL   4
#define HH   256
#define CC   2
#define FF   2048               // 4*E
#define MROWS (BB*SS)           // 32768
#define NSPLIT 8                // S-splits for kv/z

enum { EPI_NONE = 0, EPI_PHI = 1, EPI_GELU = 2, EPI_RES = 3 };

// ---------------- scratch (device globals; allocation-free) ----------------
__device__ float g_H  [(size_t)MROWS*EE];
__device__ float g_A  [(size_t)MROWS*EE];
__device__ float g_V  [(size_t)MROWS*EE];
__device__ float g_Q  [(size_t)MROWS*PP];
__device__ float g_K  [(size_t)MROWS*PP];
__device__ float g_KV [(size_t)BB*PP*EE];
__device__ float g_KVp[(size_t)NSPLIT*BB*PP*EE];
__device__ float g_Z  [(size_t)BB*PP];
__device__ float g_Zp [(size_t)NSPLIT*BB*PP];

// packed bf16x2 (along k): word = bf16(k even) | bf16(k odd)<<16
__device__ unsigned g_Hh [(size_t)MROWS*(EE/2)],  g_Hl [(size_t)MROWS*(EE/2)];
__device__ unsigned g_NMh[(size_t)MROWS*(EE/2)],  g_NMl[(size_t)MROWS*(EE/2)];
__device__ unsigned g_LNh[(size_t)MROWS*(EE/2)],  g_LNl[(size_t)MROWS*(EE/2)];
__device__ unsigned g_Mbh[(size_t)MROWS*(FF/2)],  g_Mbl[(size_t)MROWS*(FF/2)];
// pre-split transposed weights [N][K/2]
__device__ unsigned g_Wqh[(size_t)LL*PP*(EE/2)],  g_Wql_[(size_t)LL*PP*(EE/2)];
__device__ unsigned g_Wkh[(size_t)LL*PP*(EE/2)],  g_Wkl_[(size_t)LL*PP*(EE/2)];
__device__ unsigned g_Wvh[(size_t)LL*EE*(EE/2)],  g_Wvl_[(size_t)LL*EE*(EE/2)];
__device__ unsigned g_Woh[(size_t)LL*EE*(EE/2)],  g_Wol_[(size_t)LL*EE*(EE/2)];
__device__ unsigned g_W1h[(size_t)LL*FF*(EE/2)],  g_W1l_[(size_t)LL*FF*(EE/2)];
__device__ unsigned g_W2h[(size_t)LL*EE*(FF/2)],  g_W2l_[(size_t)LL*EE*(FF/2)];

// ---------------- helpers ----------------
__device__ __forceinline__ void cp_async16(void* smem, const void* gmem) {
    unsigned sa = (unsigned)__cvta_generic_to_shared(smem);
    asm volatile("cp.async.cg.shared.global [%0], [%1], 16;" :: "r"(sa), "l"(gmem));
}
__device__ __forceinline__ void cp_commit() {
    asm volatile("cp.async.commit_group;");
}
template<int N>
__device__ __forceinline__ void cp_wait() {
    asm volatile("cp.async.wait_group %0;" :: "n"(N));
}

// Split two consecutive fp32 into packed bf16x2 hi/lo. low16 = first elem.
__device__ __forceinline__ void split2(float x, float y, unsigned& hi, unsigned& lo) {
    asm("cvt.rn.bf16x2.f32 %0, %1, %2;" : "=r"(hi) : "f"(y), "f"(x));
    float hx = __uint_as_float(hi << 16);
    float hy = __uint_as_float(hi & 0xFFFF0000u);
    float lx = x - hx;
    float ly = y - hy;
    asm("cvt.rn.bf16x2.f32 %0, %1, %2;" : "=r"(lo) : "f"(ly), "f"(lx));
}

__device__ __forceinline__ void mma_bf16(float c[4], const unsigned a[4], const unsigned b[2]) {
    asm volatile(
        "mma.sync.aligned.m16n8k16.row.col.f32.bf16.bf16.f32 "
        "{%0,%1,%2,%3}, {%4,%5,%6,%7}, {%8,%9}, {%0,%1,%2,%3};"
        : "+f"(c[0]), "+f"(c[1]), "+f"(c[2]), "+f"(c[3])
        : "r"(a[0]), "r"(a[1]), "r"(a[2]), "r"(a[3]), "r"(b[0]), "r"(b[1]));
}

// ---------------- weight transpose + split: W[K][N] -> T[N][K/2] words ----------------
__global__ void wsplit_kernel(const float* __restrict__ W,
                              unsigned* __restrict__ Th, unsigned* __restrict__ Tl,
                              int K, int N) {
    const float* Wl = W + (size_t)blockIdx.z * K * N;
    unsigned* Thl = Th + (size_t)blockIdx.z * N * (K >> 1);
    unsigned* Tll = Tl + (size_t)blockIdx.z * N * (K >> 1);
    __shared__ float t[32][33];
    int k0 = blockIdx.y * 32, n0 = blockIdx.x * 32;
    int tx = threadIdx.x, ty = threadIdx.y;     // 32 x 8
    #pragma unroll
    for (int i = 0; i < 4; i++)
        t[ty + i * 8][tx] = Wl[(size_t)(k0 + ty + i * 8) * N + n0 + tx];
    __syncthreads();
    int tid = ty * 32 + tx;
    #pragma unroll
    for (int i = 0; i < 2; i++) {
        int w = tid + i * 256;
        int n = w >> 4, kp = w & 15;
        unsigned h, l;
        split2(t[2 * kp][n], t[2 * kp + 1][n], h, l);
        size_t o = (size_t)(n0 + n) * (K >> 1) + (k0 >> 1) + kp;
        Thl[o] = h;
        Tll[o] = l;
    }
}

// ---------------- embedding + positional (fp32 + packed) ----------------
__global__ void embed_kernel(const int* __restrict__ x,
                             const float* __restrict__ emb,
                             const float* __restrict__ pos,
                             float* __restrict__ H,
                             unsigned* __restrict__ Hh, unsigned* __restrict__ Hl) {
    int row = blockIdx.x;
    int s   = row & (SS - 1);
    int tok = x[row];
    const float4* e4 = (const float4*)(emb + (size_t)tok * EE);
    const float4* p4 = (const float4*)(pos + (size_t)s * EE);
    int t = threadIdx.x;                    // 128, 4 elems each
    float4 a = e4[t], b = p4[t];
    float4 o = make_float4(a.x + b.x, a.y + b.y, a.z + b.z, a.w + b.w);
    ((float4*)(H + (size_t)row * EE))[t] = o;
    unsigned h0, l0, h1, l1;
    split2(o.x, o.y, h0, l0);
    split2(o.z, o.w, h1, l1);
    size_t wo = (size_t)row * (EE / 2) + 2 * t;
    Hh[wo] = h0; Hh[wo + 1] = h1;
    Hl[wo] = l0; Hl[wo + 1] = l1;
}

// ---------------- packed-operand bf16x2 tensor-core GEMM ----------------
// C[M,N] = A[M,K] @ B[K,N]. A packed hi/lo [M][K/2] words;
// B packed transposed hi/lo [N][K/2] words. BK=32, 3-stage cp.async.
template<int BM, int BN, int WM, int WN, int EPI, bool WF32, bool WPACK>
__global__ void __launch_bounds__((BM/WM)*(BN/WN)*32)
gemm_pk(int M, int N, int K,
        const unsigned* __restrict__ Ah, const unsigned* __restrict__ Al,
        const unsigned* __restrict__ Bh, const unsigned* __restrict__ Bl,
        const float* __restrict__ bias,
        const float* __restrict__ res,
        float* __restrict__ C,
        unsigned* __restrict__ Ch, unsigned* __restrict__ Cl)
{
    constexpr int WARPS_M = BM / WM;
    constexpr int WARPS_N = BN / WN;
    constexpr int NTH = WARPS_M * WARPS_N * 32;
    constexpr int LDW = 20;            // 16 words + 4 pad per row
    constexpr int ASZ = BM * LDW;
    constexpr int BSZ = BN * LDW;
    constexpr int MT = WM / 16;
    constexpr int NT = WN / 8;
    constexpr int A_CNT = BM * 4 / NTH;   // 16B chunks per stage per array
    constexpr int B_CNT = BN * 4 / NTH;

    extern __shared__ unsigned smw[];
    unsigned* Ash = smw;
    unsigned* Asl = smw + 3 * ASZ;
    unsigned* Bsh = smw + 6 * ASZ;
    unsigned* Bsl = smw + 6 * ASZ + 3 * BSZ;

    const int tid  = threadIdx.x;
    const int lane = tid & 31;
    const int warp = tid >> 5;
    const int wm   = warp / WARPS_N;
    const int wn   = warp % WARPS_N;
    const int lr   = lane >> 2;
    const int lc   = lane & 3;
    const int row0 = blockIdx.y * BM;
    const int col0 = blockIdx.x * BN;
    const int KW   = K >> 1;
    const int KT   = K / 32;

    float acc[MT][NT][4];
    #pragma unroll
    for (int i = 0; i < MT; i++)
        #pragma unroll
        for (int j = 0; j < NT; j++)
            #pragma unroll
            for (int q = 0; q < 4; q++) acc[i][j][q] = 0.f;

    auto issue = [&](int kt, int st) {
        int goff = kt * 16;
        #pragma unroll
        for (int i = 0; i < A_CNT; i++) {
            int idx = tid + i * NTH;
            int r = idx >> 2, c = (idx & 3) * 4;
            size_t g = (size_t)(row0 + r) * KW + goff + c;
            cp_async16(Ash + st * ASZ + r * LDW + c, Ah + g);
            cp_async16(Asl + st * ASZ + r * LDW + c, Al + g);
        }
        #pragma unroll
        for (int i = 0; i < B_CNT; i++) {
            int idx = tid + i * NTH;
            int r = idx >> 2, c = (idx & 3) * 4;
            size_t g = (size_t)(col0 + r) * KW + goff + c;
            cp_async16(Bsh + st * BSZ + r * LDW + c, Bh + g);
            cp_async16(Bsl + st * BSZ + r * LDW + c, Bl + g);
        }
    };

    auto compute = [&](int st) {
        const unsigned* Ah_ = Ash + st * ASZ;
        const unsigned* Al_ = Asl + st * ASZ;
        const unsigned* Bh_ = Bsh + st * BSZ;
        const unsigned* Bl_ = Bsl + st * BSZ;
        #pragma unroll
        for (int kk = 0; kk < 2; kk++) {
            unsigned ah[MT][4], al[MT][4], bh[NT][2], bl[NT][2];
            #pragma unroll
            for (int i = 0; i < MT; i++) {
                int base = (wm * WM + i * 16 + lr) * LDW + kk * 8 + lc;
                ah[i][0] = Ah_[base];           al[i][0] = Al_[base];
                ah[i][1] = Ah_[base + 8 * LDW]; al[i][1] = Al_[base + 8 * LDW];
                ah[i][2] = Ah_[base + 4];       al[i][2] = Al_[base + 4];
                ah[i][3] = Ah_[base + 8 * LDW + 4]; al[i][3] = Al_[base + 8 * LDW + 4];
            }
            #pragma unroll
            for (int j = 0; j < NT; j++) {
                int bbase = (wn * WN + j * 8 + lr) * LDW + kk * 8 + lc;
                bh[j][0] = Bh_[bbase];     bl[j][0] = Bl_[bbase];
                bh[j][1] = Bh_[bbase + 4]; bl[j][1] = Bl_[bbase + 4];
            }
            #pragma unroll
            for (int i = 0; i < MT; i++)
                #pragma unroll
                for (int j = 0; j < NT; j++) {
                    mma_bf16(acc[i][j], ah[i], bh[j]);
                    mma_bf16(acc[i][j], ah[i], bl[j]);
                    mma_bf16(acc[i][j], al[i], bh[j]);
                }
        }
    };

    issue(0, 0); cp_commit();
    issue(1, 1); cp_commit();
    cp_wait<1>();
    __syncthreads();

    for (int kt = 0; kt < KT; kt++) {
        if (kt + 2 < KT) issue(kt + 2, (kt + 2) % 3);
        cp_commit();
        compute(kt % 3);
        cp_wait<1>();
        __syncthreads();
    }

    auto epi = [&](float v, int rr, int cc) -> float {
        if (EPI == EPI_PHI) {
            return v > 0.f ? v + 1.f : expf(v);
        } else if (EPI == EPI_GELU) {
            v += bias[cc];
            float u = 0.7978845608028654f * (v + 0.044715f * v * v * v);
            return 0.5f * v * (1.f + tanhf(u));
        } else if (EPI == EPI_RES) {
            return v + bias[cc] + res[(size_t)rr * N + cc];
        }
        return v;
    };

    #pragma unroll
    for (int i = 0; i < MT; i++) {
        #pragma unroll
        for (int j = 0; j < NT; j++) {
            int rr = row0 + wm * WM + i * 16 + lr;
            int cc = col0 + wn * WN + j * 8 + 2 * lc;
            float e00 = epi(acc[i][j][0], rr, cc);
            float e01 = epi(acc[i][j][1], rr, cc + 1);
            float e10 = epi(acc[i][j][2], rr + 8, cc);
            float e11 = epi(acc[i][j][3], rr + 8, cc + 1);
            if (WF32) {
                *(float2*)(C + (size_t)rr * N + cc)       = make_float2(e00, e01);
                *(float2*)(C + (size_t)(rr + 8) * N + cc) = make_float2(e10, e11);
            }
            if (WPACK) {
                unsigned h, l;
                split2(e00, e01, h, l);
                size_t w0 = (size_t)rr * (N >> 1) + (cc >> 1);
                Ch[w0] = h; Cl[w0] = l;
                split2(e10, e11, h, l);
                size_t w1 = (size_t)(rr + 8) * (N >> 1) + (cc >> 1);
                Ch[w1] = h; Cl[w1] = l;
            }
        }
    }
}

// ---------------- kv partials: split over S ----------------
__global__ void __launch_bounds__(256)
kv_kernel(const float* __restrict__ Kp, const float* __restrict__ V,
          float* __restrict__ KVp)
{
    int b  = blockIdx.y;
    int f0 = blockIdx.x * 64;
    int sp = blockIdx.z;
    const float* Kb = Kp + (size_t)b * SS * PP;
    const float* Vb = V  + (size_t)b * SS * EE;

    __shared__ float Ks[32 * 64];
    __shared__ float Vs[32 * 64];
    int tid = threadIdx.x;
    int tx = tid % 16, ty = tid / 16;

    float acc[4][4];
    #pragma unroll
    for (int i = 0; i < 4; i++)
        #pragma unroll
        for (int j = 0; j < 4; j++) acc[i][j] = 0.f;

    int sbeg = sp * (SS / NSPLIT), send = sbeg + (SS / NSPLIT);
    for (int s0 = sbeg; s0 < send; s0 += 32) {
        #pragma unroll
        for (int i = 0; i < 2; i++) {
            int idx = tid + i * 256;
            int r = idx / 16, c4 = idx % 16;
            *(float4*)(Ks + r * 64 + c4 * 4) =
                *(const float4*)(Kb + (size_t)(s0 + r) * PP + c4 * 4);
            *(float4*)(Vs + r * 64 + c4 * 4) =
                *(const float4*)(Vb + (size_t)(s0 + r) * EE + f0 + c4 * 4);
        }
        __syncthreads();
        #pragma unroll
        for (int k = 0; k < 32; k++) {
            float rp[4], rv[4];
            #pragma unroll
            for (int i = 0; i < 4; i++) rp[i] = Ks[k * 64 + ty * 4 + i];
            #pragma unroll
            for (int j = 0; j < 4; j++) rv[j] = Vs[k * 64 + tx * 4 + j];
            #pragma unroll
            for (int i = 0; i < 4; i++)
                #pragma unroll
                for (int j = 0; j < 4; j++)
                    acc[i][j] = fmaf(rp[i], rv[j], acc[i][j]);
        }
        __syncthreads();
    }
    float* out = KVp + (size_t)sp * BB * PP * EE;
    #pragma unroll
    for (int i = 0; i < 4; i++)
        #pragma unroll
        for (int j = 0; j < 4; j++)
            out[((size_t)b * PP + ty * 4 + i) * EE + f0 + tx * 4 + j] = acc[i][j];
}

__global__ void reduce_kv(const float* __restrict__ KVp, float* __restrict__ KV) {
    size_t idx = (size_t)blockIdx.x * 256 + threadIdx.x;
    float s = 0.f;
    #pragma unroll
    for (int sp = 0; sp < NSPLIT; sp++)
        s += KVp[(size_t)sp * BB * PP * EE + idx];
    KV[idx] = s;
}

// ---------------- z partials ----------------
__global__ void z_kernel(const float* __restrict__ Kp, float* __restrict__ Zp) {
    int b = blockIdx.x, sp = blockIdx.y;
    int tid = threadIdx.x;
    int p = tid & 63, g = tid >> 6;
    const float* Kb = Kp + (size_t)b * SS * PP;
    float acc = 0.f;
    int sbeg = sp * (SS / NSPLIT), send = sbeg + (SS / NSPLIT);
    for (int s = sbeg + g; s < send; s += 4) acc += Kb[(size_t)s * PP + p];
    __shared__ float smem[256];
    smem[tid] = acc;
    __syncthreads();
    if (g == 0)
        Zp[(size_t)sp * BB * PP + b * PP + p] =
            smem[p] + smem[64 + p] + smem[128 + p] + smem[192 + p];
}

__global__ void reduce_z(const float* __restrict__ Zp, float* __restrict__ Z) {
    int idx = blockIdx.x * 256 + threadIdx.x;
    if (idx < BB * PP) {
        float s = 0.f;
        #pragma unroll
        for (int sp = 0; sp < NSPLIT; sp++) s += Zp[sp * BB * PP + idx];
        Z[idx] = s;
    }
}

// ---------------- attn = (phi_q @ KV) / (phi_q . z + eps), packed output ----------------
__global__ void __launch_bounds__(256)
num_kernel(const float* __restrict__ Qp, const float* __restrict__ KV,
           const float* __restrict__ Z,
           unsigned* __restrict__ Oh, unsigned* __restrict__ Ol)
{
    int b  = blockIdx.z;
    int s0 = blockIdx.y * 64;
    int f0 = blockIdx.x * 128;

    __shared__ float Qs[64 * 64];
    __shared__ float KVs[64 * 128];
    __shared__ float Zs[64];

    int tid = threadIdx.x;
    const float* Qb = Qp + ((size_t)b * SS + s0) * PP;
    #pragma unroll
    for (int i = 0; i < 4; i++) {
        int idx = tid + i * 256;
        int r = idx / 16, c4 = idx % 16;
        *(float4*)(Qs + r * 64 + c4 * 4) =
            *(const float4*)(Qb + (size_t)r * PP + c4 * 4);
    }
    const float* KVb = KV + (size_t)b * PP * EE;
    #pragma unroll
    for (int i = 0; i < 8; i++) {
        int idx = tid + i * 256;
        int r = idx / 32, c4 = idx % 32;
        *(float4*)(KVs + r * 128 + c4 * 4) =
            *(const float4*)(KVb + (size_t)r * EE + f0 + c4 * 4);
    }
    if (tid < 64) Zs[tid] = Z[b * PP + tid];
    __syncthreads();

    int tx = tid % 16, ty = tid / 16;
    float acc[4][8];
    float den[4] = {0.f, 0.f, 0.f, 0.f};
    #pragma unroll
    for (int i = 0; i < 4; i++)
        #pragma unroll
        for (int j = 0; j < 8; j++) acc[i][j] = 0.f;

    #pragma unroll 8
    for (int k = 0; k < 64; k++) {
        float rq[4];
        #pragma unroll
        for (int i = 0; i < 4; i++) rq[i] = Qs[(ty * 4 + i) * 64 + k];
        float rz = Zs[k];
        #pragma unroll
        for (int i = 0; i < 4; i++) den[i] = fmaf(rq[i], rz, den[i]);
        #pragma unroll
        for (int j = 0; j < 8; j++) {
            float rk = KVs[k * 128 + tx * 8 + j];
            #pragma unroll
            for (int i = 0; i < 4; i++) acc[i][j] = fmaf(rq[i], rk, acc[i][j]);
        }
    }

    #pragma unroll
    for (int i = 0; i < 4; i++) {
        float inv = 1.f / (den[i] + 1e-6f);
        size_t row = (size_t)b * SS + s0 + ty * 4 + i;
        size_t wbase = row * (EE / 2) + f0 / 2 + tx * 4;
        #pragma unroll
        for (int jw = 0; jw < 4; jw++) {
            unsigned h, l;
            split2(acc[i][2 * jw] * inv, acc[i][2 * jw + 1] * inv, h, l);
            Oh[wbase + jw] = h;
            Ol[wbase + jw] = l;
        }
    }
}

// ---------------- layernorm: read fp32, write packed ----------------
__global__ void ln_kernel(const float* __restrict__ X,
                          const float* __restrict__ gam,
                          const float* __restrict__ bet,
                          unsigned* __restrict__ Oh, unsigned* __restrict__ Ol) {
    int row = blockIdx.x;
    const float* xr = X + (size_t)row * EE;
    int tid = threadIdx.x;                 // 128
    float4 v = ((const float4*)xr)[tid];
    float s = v.x + v.y + v.z + v.w;
    float q = v.x * v.x + v.y * v.y + v.z * v.z + v.w * v.w;
    #pragma unroll
    for (int o = 16; o; o >>= 1) {
        s += __shfl_xor_sync(0xffffffffu, s, o);
        q += __shfl_xor_sync(0xffffffffu, q, o);
    }
    __shared__ float ss[4], qq[4];
    int w = tid >> 5;
    if ((tid & 31) == 0) { ss[w] = s; qq[w] = q; }
    __syncthreads();
    s = ss[0] + ss[1] + ss[2] + ss[3];
    q = qq[0] + qq[1] + qq[2] + qq[3];
    float mu  = s * (1.f / EE);
    float var = q * (1.f / EE) - mu * mu;
    float inv = rsqrtf(var + 1e-5f);
    float4 g4 = ((const float4*)gam)[tid];
    float4 b4 = ((const float4*)bet)[tid];
    float o0 = (v.x - mu) * inv * g4.x + b4.x;
    float o1 = (v.y - mu) * inv * g4.y + b4.y;
    float o2 = (v.z - mu) * inv * g4.z + b4.z;
    float o3 = (v.w - mu) * inv * g4.w + b4.w;
    unsigned h0, l0, h1, l1;
    split2(o0, o1, h0, l0);
    split2(o2, o3, h1, l1);
    size_t wo = (size_t)row * (EE / 2) + 2 * tid;
    Oh[wo] = h0; Oh[wo + 1] = h1;
    Ol[wo] = l0; Ol[wo + 1] = l1;
}

// ---------------- head ----------------
__global__ void head_kernel(const float* __restrict__ Hm,
                            const float* __restrict__ Wh1,
                            const float* __restrict__ bh1,
                            const float* __restrict__ Wh2,
                            const float* __restrict__ bh2,
                            float* __restrict__ out) {
    int b = blockIdx.x;
    int tid = threadIdx.x;
    const float* hr = Hm + (size_t)b * SS * EE;
    float acc = bh1[tid];
    for (int e = 0; e < EE; e++) acc = fmaf(hr[e], Wh1[e * HH + tid], acc);
    acc = fmaxf(acc, 0.f);
    __shared__ float hid[HH];
    hid[tid] = acc;
    __syncthreads();
    if (tid < CC) {
        float a = bh2[tid];
        for (int h = 0; h < HH; h++) a = fmaf(hid[h], Wh2[h * CC + tid], a);
        out[b * CC + tid] = a;
    }
}

// ---------------- launch ----------------
static size_t gemm_smem(int BM, int BN) {
    return (size_t)(3 * (BM * 20 * 2 + BN * 20 * 2)) * 4;
}

extern "C" void kernel_launch(void* const* d_in, const int* in_sizes, int n_in,
                              void* d_out, int out_size) {
    const int*   x    = (const int*)  d_in[0];
    const float* emb  = (const float*)d_in[1];
    const float* pos  = (const float*)d_in[2];
    const float* Wq   = (const float*)d_in[3];
    const float* Wk   = (const float*)d_in[4];
    const float* Wv   = (const float*)d_in[5];
    const float* Wo   = (const float*)d_in[6];
    const float* ln_g = (const float*)d_in[7];
    const float* ln_b = (const float*)d_in[8];
    const float* W1   = (const float*)d_in[9];
    const float* b1   = (const float*)d_in[10];
    const float* W2   = (const float*)d_in[11];
    const float* b2   = (const float*)d_in[12];
    const float* Wh1  = (const float*)d_in[13];
    const float* bh1  = (const float*)d_in[14];
    const float* Wh2  = (const float*)d_in[15];
    const float* bh2  = (const float*)d_in[16];
    float* out = (float*)d_out;

    float *H, *A, *V, *Q, *Kq, *KV, *KVp, *Z, *Zp;
    cudaGetSymbolAddress((void**)&H,   g_H);
    cudaGetSymbolAddress((void**)&A,   g_A);
    cudaGetSymbolAddress((void**)&V,   g_V);
    cudaGetSymbolAddress((void**)&Q,   g_Q);
    cudaGetSymbolAddress((void**)&Kq,  g_K);
    cudaGetSymbolAddress((void**)&KV,  g_KV);
    cudaGetSymbolAddress((void**)&KVp, g_KVp);
    cudaGetSymbolAddress((void**)&Z,   g_Z);
    cudaGetSymbolAddress((void**)&Zp,  g_Zp);

    unsigned *Hh, *Hl, *NMh, *NMl, *LNh, *LNl, *Mbh, *Mbl;
    cudaGetSymbolAddress((void**)&Hh,  g_Hh);  cudaGetSymbolAddress((void**)&Hl,  g_Hl);
    cudaGetSymbolAddress((void**)&NMh, g_NMh); cudaGetSymbolAddress((void**)&NMl, g_NMl);
    cudaGetSymbolAddress((void**)&LNh, g_LNh); cudaGetSymbolAddress((void**)&LNl, g_LNl);
    cudaGetSymbolAddress((void**)&Mbh, g_Mbh); cudaGetSymbolAddress((void**)&Mbl, g_Mbl);

    unsigned *Wqh, *Wql, *Wkh, *Wkl, *Wvh, *Wvl, *Woh, *Wol, *W1h, *W1l, *W2h, *W2l;
    cudaGetSymbolAddress((void**)&Wqh, g_Wqh); cudaGetSymbolAddress((void**)&Wql, g_Wql_);
    cudaGetSymbolAddress((void**)&Wkh, g_Wkh); cudaGetSymbolAddress((void**)&Wkl, g_Wkl_);
    cudaGetSymbolAddress((void**)&Wvh, g_Wvh); cudaGetSymbolAddress((void**)&Wvl, g_Wvl_);
    cudaGetSymbolAddress((void**)&Woh, g_Woh); cudaGetSymbolAddress((void**)&Wol, g_Wol_);
    cudaGetSymbolAddress((void**)&W1h, g_W1h); cudaGetSymbolAddress((void**)&W1l, g_W1l_);
    cudaGetSymbolAddress((void**)&W2h, g_W2h); cudaGetSymbolAddress((void**)&W2l, g_W2l_);

    const size_t smQK  = gemm_smem(128, 64);    //  92,160 B
    const size_t smBIG = gemm_smem(128, 256);   // 184,320 B
    cudaFuncSetAttribute(gemm_pk<128, 64, 32, 32, EPI_PHI, true, false>,
                         cudaFuncAttributeMaxDynamicSharedMemorySize, (int)smQK);
    cudaFuncSetAttribute(gemm_pk<128, 256, 64, 32, EPI_NONE, true, false>,
                         cudaFuncAttributeMaxDynamicSharedMemorySize, (int)smBIG);
    cudaFuncSetAttribute(gemm_pk<128, 256, 64, 32, EPI_GELU, false, true>,
                         cudaFuncAttributeMaxDynamicSharedMemorySize, (int)smBIG);
    cudaFuncSetAttribute(gemm_pk<128, 256, 64, 32, EPI_RES, true, true>,
                         cudaFuncAttributeMaxDynamicSharedMemorySize, (int)smBIG);

    // one-time weight transpose+split (all layers)
    dim3 wt(32, 8);
    wsplit_kernel<<<dim3(PP / 32, EE / 32, LL), wt>>>(Wq, Wqh, Wql, EE, PP);
    wsplit_kernel<<<dim3(PP / 32, EE / 32, LL), wt>>>(Wk, Wkh, Wkl, EE, PP);
    wsplit_kernel<<<dim3(EE / 32, EE / 32, LL), wt>>>(Wv, Wvh, Wvl, EE, EE);
    wsplit_kernel<<<dim3(EE / 32, EE / 32, LL), wt>>>(Wo, Woh, Wol, EE, EE);
    wsplit_kernel<<<dim3(FF / 32, EE / 32, LL), wt>>>(W1, W1h, W1l, EE, FF);
    wsplit_kernel<<<dim3(EE / 32, FF / 32, LL), wt>>>(W2, W2h, W2l, FF, EE);

    embed_kernel<<<MROWS, 128>>>(x, emb, pos, H, Hh, Hl);

    for (int l = 0; l < LL; l++) {
        size_t oQK = (size_t)l * PP * (EE / 2);
        size_t oV  = (size_t)l * EE * (EE / 2);
        size_t oW1 = (size_t)l * FF * (EE / 2);
        size_t oW2 = (size_t)l * EE * (FF / 2);

        gemm_pk<128, 64, 32, 32, EPI_PHI, true, false>
            <<<dim3(PP / 64, MROWS / 128), 256, smQK>>>(
                MROWS, PP, EE, Hh, Hl, Wqh + oQK, Wql + oQK,
                nullptr, nullptr, Q, nullptr, nullptr);
        gemm_pk<128, 64, 32, 32, EPI_PHI, true, false>
            <<<dim3(PP / 64, MROWS / 128), 256, smQK>>>(
                MROWS, PP, EE, Hh, Hl, Wkh + oQK, Wkl + oQK,
                nullptr, nullptr, Kq, nullptr, nullptr);
        gemm_pk<128, 256, 64, 32, EPI_NONE, true, false>
            <<<dim3(EE / 256, MROWS / 128), 512, smBIG>>>(
                MROWS, EE, EE, Hh, Hl, Wvh + oV, Wvl + oV,
                nullptr, nullptr, V, nullptr, nullptr);

        kv_kernel<<<dim3(EE / 64, BB, NSPLIT), 256>>>(Kq, V, KVp);
        z_kernel<<<dim3(BB, NSPLIT), 256>>>(Kq, Zp);
        reduce_kv<<<(BB * PP * EE) / 256, 256>>>(KVp, KV);
        reduce_z<<<2, 256>>>(Zp, Z);
        num_kernel<<<dim3(EE / 128, SS / 64, BB), 256>>>(Q, KV, Z, NMh, NMl);

        gemm_pk<128, 256, 64, 32, EPI_NONE, true, false>
            <<<dim3(EE / 256, MROWS / 128), 512, smBIG>>>(
                MROWS, EE, EE, NMh, NMl, Woh + oV, Wol + oV,
                nullptr, nullptr, A, nullptr, nullptr);

        ln_kernel<<<MROWS, 128>>>(A, ln_g + (size_t)l * EE, ln_b + (size_t)l * EE,
                                  LNh, LNl);

        gemm_pk<128, 256, 64, 32, EPI_GELU, false, true>
            <<<dim3(FF / 256, MROWS / 128), 512, smBIG>>>(
                MROWS, FF, EE, LNh, LNl, W1h + oW1, W1l + oW1,
                b1 + (size_t)l * FF, nullptr, nullptr, Mbh, Mbl);
        gemm_pk<128, 256, 64, 32, EPI_RES, true, true>
            <<<dim3(EE / 256, MROWS / 128), 512, smBIG>>>(
                MROWS, EE, FF, Mbh, Mbl, W2h + oW2, W2l + oW2,
                b2 + (size_t)l * EE, H, H, Hh, Hl);
    }

    head_kernel<<<BB, HH>>>(H, Wh1, bh1, Wh2, bh2, out);
}

// round 7
// speedup vs baseline: 2.4223x; 1.0300x over previous
#include <cuda_runtime.h>
#include <math.h>

// Problem constants
#define BB   8
#define SS   4096
#define EE   512
#define PP   64
#define LL   4
#define HH   256
#define CC   2
#define FF   2048               // 4*E
#define MROWS (BB*SS)           // 32768
#define NSPLIT 8                // S-splits for kv/z

enum { EPI_NONE = 0, EPI_PHI = 1, EPI_GELU = 2, EPI_RES = 3, EPI_DIV = 4 };

// ---------------- scratch (device globals; allocation-free) ----------------
__device__ float g_H  [(size_t)MROWS*EE];
__device__ float g_A  [(size_t)MROWS*EE];
__device__ float g_V  [(size_t)MROWS*EE];
__device__ float g_Q  [(size_t)MROWS*PP];
__device__ float g_K  [(size_t)MROWS*PP];
__device__ float g_KV [(size_t)BB*PP*EE];
__device__ float g_KVp[(size_t)NSPLIT*BB*PP*EE];
__device__ float g_Z  [(size_t)BB*PP];
__device__ float g_Zp [(size_t)NSPLIT*BB*PP];
__device__ float g_DEN[(size_t)MROWS];

// packed bf16x2 (along k): word = bf16(k even) | bf16(k odd)<<16
__device__ unsigned g_Hh [(size_t)MROWS*(EE/2)],  g_Hl [(size_t)MROWS*(EE/2)];
__device__ unsigned g_NMh[(size_t)MROWS*(EE/2)],  g_NMl[(size_t)MROWS*(EE/2)];
__device__ unsigned g_LNh[(size_t)MROWS*(EE/2)],  g_LNl[(size_t)MROWS*(EE/2)];
__device__ unsigned g_Mbh[(size_t)MROWS*(FF/2)],  g_Mbl[(size_t)MROWS*(FF/2)];
__device__ unsigned g_Qh [(size_t)MROWS*(PP/2)],  g_Ql [(size_t)MROWS*(PP/2)];
__device__ unsigned g_KVTh[(size_t)BB*EE*(PP/2)], g_KVTl[(size_t)BB*EE*(PP/2)];
// pre-split transposed weights [N][K/2]
__device__ unsigned g_Wqh[(size_t)LL*PP*(EE/2)],  g_Wql_[(size_t)LL*PP*(EE/2)];
__device__ unsigned g_Wkh[(size_t)LL*PP*(EE/2)],  g_Wkl_[(size_t)LL*PP*(EE/2)];
__device__ unsigned g_Wvh[(size_t)LL*EE*(EE/2)],  g_Wvl_[(size_t)LL*EE*(EE/2)];
__device__ unsigned g_Woh[(size_t)LL*EE*(EE/2)],  g_Wol_[(size_t)LL*EE*(EE/2)];
__device__ unsigned g_W1h[(size_t)LL*FF*(EE/2)],  g_W1l_[(size_t)LL*FF*(EE/2)];
__device__ unsigned g_W2h[(size_t)LL*EE*(FF/2)],  g_W2l_[(size_t)LL*EE*(FF/2)];

// ---------------- helpers ----------------
__device__ __forceinline__ void cp_async16(void* smem, const void* gmem) {
    unsigned sa = (unsigned)__cvta_generic_to_shared(smem);
    asm volatile("cp.async.cg.shared.global [%0], [%1], 16;" :: "r"(sa), "l"(gmem));
}
__device__ __forceinline__ void cp_commit() {
    asm volatile("cp.async.commit_group;");
}
template<int N>
__device__ __forceinline__ void cp_wait() {
    asm volatile("cp.async.wait_group %0;" :: "n"(N));
}

// Split two consecutive fp32 into packed bf16x2 hi/lo. low16 = first elem.
__device__ __forceinline__ void split2(float x, float y, unsigned& hi, unsigned& lo) {
    asm("cvt.rn.bf16x2.f32 %0, %1, %2;" : "=r"(hi) : "f"(y), "f"(x));
    float hx = __uint_as_float(hi << 16);
    float hy = __uint_as_float(hi & 0xFFFF0000u);
    float lx = x - hx;
    float ly = y - hy;
    asm("cvt.rn.bf16x2.f32 %0, %1, %2;" : "=r"(lo) : "f"(ly), "f"(lx));
}

__device__ __forceinline__ void mma_bf16(float c[4], const unsigned a[4], const unsigned b[2]) {
    asm volatile(
        "mma.sync.aligned.m16n8k16.row.col.f32.bf16.bf16.f32 "
        "{%0,%1,%2,%3}, {%4,%5,%6,%7}, {%8,%9}, {%0,%1,%2,%3};"
        : "+f"(c[0]), "+f"(c[1]), "+f"(c[2]), "+f"(c[3])
        : "r"(a[0]), "r"(a[1]), "r"(a[2]), "r"(a[3]), "r"(b[0]), "r"(b[1]));
}

// ---------------- transpose + split: W[K][N] -> T[N][K/2] words ----------------
// blockIdx.z indexes a matrix of size K*N (layer or batch).
__global__ void wsplit_kernel(const float* __restrict__ W,
                              unsigned* __restrict__ Th, unsigned* __restrict__ Tl,
                              int K, int N) {
    const float* Wl = W + (size_t)blockIdx.z * K * N;
    unsigned* Thl = Th + (size_t)blockIdx.z * N * (K >> 1);
    unsigned* Tll = Tl + (size_t)blockIdx.z * N * (K >> 1);
    __shared__ float t[32][33];
    int k0 = blockIdx.y * 32, n0 = blockIdx.x * 32;
    int tx = threadIdx.x, ty = threadIdx.y;     // 32 x 8
    #pragma unroll
    for (int i = 0; i < 4; i++)
        t[ty + i * 8][tx] = Wl[(size_t)(k0 + ty + i * 8) * N + n0 + tx];
    __syncthreads();
    int tid = ty * 32 + tx;
    #pragma unroll
    for (int i = 0; i < 2; i++) {
        int w = tid + i * 256;
        int n = w >> 4, kp = w & 15;
        unsigned h, l;
        split2(t[2 * kp][n], t[2 * kp + 1][n], h, l);
        size_t o = (size_t)(n0 + n) * (K >> 1) + (k0 >> 1) + kp;
        Thl[o] = h;
        Tll[o] = l;
    }
}

// ---------------- embedding + positional (fp32 + packed) ----------------
__global__ void embed_kernel(const int* __restrict__ x,
                             const float* __restrict__ emb,
                             const float* __restrict__ pos,
                             float* __restrict__ H,
                             unsigned* __restrict__ Hh, unsigned* __restrict__ Hl) {
    int row = blockIdx.x;
    int s   = row & (SS - 1);
    int tok = x[row];
    const float4* e4 = (const float4*)(emb + (size_t)tok * EE);
    const float4* p4 = (const float4*)(pos + (size_t)s * EE);
    int t = threadIdx.x;                    // 128, 4 elems each
    float4 a = e4[t], b = p4[t];
    float4 o = make_float4(a.x + b.x, a.y + b.y, a.z + b.z, a.w + b.w);
    ((float4*)(H + (size_t)row * EE))[t] = o;
    unsigned h0, l0, h1, l1;
    split2(o.x, o.y, h0, l0);
    split2(o.z, o.w, h1, l1);
    size_t wo = (size_t)row * (EE / 2) + 2 * t;
    Hh[wo] = h0; Hh[wo + 1] = h1;
    Hl[wo] = l0; Hl[wo + 1] = l1;
}

// ---------------- packed-operand bf16x2 tensor-core GEMM ----------------
// C[M,N] = A[M,K] @ B[K,N]. A packed hi/lo [M][K/2] words;
// B packed transposed hi/lo [N][K/2] words. BK=32, 3-stage cp.async.
// BATCHB: B is per-batch (4096 rows of A per batch), offset b*N*(K/2).
template<int BM, int BN, int WM, int WN, int EPI, bool WF32, bool WPACK, bool BATCHB>
__global__ void __launch_bounds__((BM/WM)*(BN/WN)*32)
gemm_pk(int M, int N, int K,
        const unsigned* __restrict__ Ah, const unsigned* __restrict__ Al,
        const unsigned* __restrict__ Bh, const unsigned* __restrict__ Bl,
        const float* __restrict__ bias,        // bias[N], or inv[M] for EPI_DIV
        const float* __restrict__ res,
        float* __restrict__ C,
        unsigned* __restrict__ Ch, unsigned* __restrict__ Cl)
{
    constexpr int WARPS_M = BM / WM;
    constexpr int WARPS_N = BN / WN;
    constexpr int NTH = WARPS_M * WARPS_N * 32;
    constexpr int LDW = 20;            // 16 words + 4 pad per row
    constexpr int ASZ = BM * LDW;
    constexpr int BSZ = BN * LDW;
    constexpr int MT = WM / 16;
    constexpr int NT = WN / 8;
    constexpr int A_CNT = BM * 4 / NTH;   // 16B chunks per stage per array
    constexpr int B_CNT = BN * 4 / NTH;

    extern __shared__ unsigned smw[];
    unsigned* Ash = smw;
    unsigned* Asl = smw + 3 * ASZ;
    unsigned* Bsh = smw + 6 * ASZ;
    unsigned* Bsl = smw + 6 * ASZ + 3 * BSZ;

    const int tid  = threadIdx.x;
    const int lane = tid & 31;
    const int warp = tid >> 5;
    const int wm   = warp / WARPS_N;
    const int wn   = warp % WARPS_N;
    const int lr   = lane >> 2;
    const int lc   = lane & 3;
    const int row0 = blockIdx.y * BM;
    const int col0 = blockIdx.x * BN;
    const int KW   = K >> 1;
    const int KT   = K / 32;

    const unsigned* Bhp = Bh;
    const unsigned* Blp = Bl;
    if (BATCHB) {
        size_t boff = (size_t)(blockIdx.y / (SS / BM)) * N * KW;
        Bhp += boff;
        Blp += boff;
    }

    float acc[MT][NT][4];
    #pragma unroll
    for (int i = 0; i < MT; i++)
        #pragma unroll
        for (int j = 0; j < NT; j++)
            #pragma unroll
            for (int q = 0; q < 4; q++) acc[i][j][q] = 0.f;

    auto issue = [&](int kt, int st) {
        int goff = kt * 16;
        #pragma unroll
        for (int i = 0; i < A_CNT; i++) {
            int idx = tid + i * NTH;
            int r = idx >> 2, c = (idx & 3) * 4;
            size_t g = (size_t)(row0 + r) * KW + goff + c;
            cp_async16(Ash + st * ASZ + r * LDW + c, Ah + g);
            cp_async16(Asl + st * ASZ + r * LDW + c, Al + g);
        }
        #pragma unroll
        for (int i = 0; i < B_CNT; i++) {
            int idx = tid + i * NTH;
            int r = idx >> 2, c = (idx & 3) * 4;
            size_t g = (size_t)(col0 + r) * KW + goff + c;
            cp_async16(Bsh + st * BSZ + r * LDW + c, Bhp + g);
            cp_async16(Bsl + st * BSZ + r * LDW + c, Blp + g);
        }
    };

    auto compute = [&](int st) {
        const unsigned* Ah_ = Ash + st * ASZ;
        const unsigned* Al_ = Asl + st * ASZ;
        const unsigned* Bh_ = Bsh + st * BSZ;
        const unsigned* Bl_ = Bsl + st * BSZ;
        #pragma unroll
        for (int kk = 0; kk < 2; kk++) {
            unsigned ah[MT][4], al[MT][4];
            #pragma unroll
            for (int i = 0; i < MT; i++) {
                int base = (wm * WM + i * 16 + lr) * LDW + kk * 8 + lc;
                ah[i][0] = Ah_[base];               al[i][0] = Al_[base];
                ah[i][1] = Ah_[base + 8 * LDW];     al[i][1] = Al_[base + 8 * LDW];
                ah[i][2] = Ah_[base + 4];           al[i][2] = Al_[base + 4];
                ah[i][3] = Ah_[base + 8 * LDW + 4]; al[i][3] = Al_[base + 8 * LDW + 4];
            }
            #pragma unroll
            for (int j = 0; j < NT; j++) {
                int bbase = (wn * WN + j * 8 + lr) * LDW + kk * 8 + lc;
                unsigned bh[2], bl[2];
                bh[0] = Bh_[bbase];     bl[0] = Bl_[bbase];
                bh[1] = Bh_[bbase + 4]; bl[1] = Bl_[bbase + 4];
                #pragma unroll
                for (int i = 0; i < MT; i++) {
                    mma_bf16(acc[i][j], ah[i], bh);
                    mma_bf16(acc[i][j], ah[i], bl);
                    mma_bf16(acc[i][j], al[i], bh);
                }
            }
        }
    };

    issue(0, 0); cp_commit();
    issue(1, 1); cp_commit();
    cp_wait<1>();
    __syncthreads();

    for (int kt = 0; kt < KT; kt++) {
        if (kt + 2 < KT) issue(kt + 2, (kt + 2) % 3);
        cp_commit();
        compute(kt % 3);
        cp_wait<1>();
        __syncthreads();
    }

    auto epi = [&](float v, int rr, int cc) -> float {
        if (EPI == EPI_PHI) {
            return v > 0.f ? v + 1.f : expf(v);
        } else if (EPI == EPI_GELU) {
            v += bias[cc];
            float u = 0.7978845608028654f * (v + 0.044715f * v * v * v);
            return 0.5f * v * (1.f + tanhf(u));
        } else if (EPI == EPI_RES) {
            return v + bias[cc] + res[(size_t)rr * N + cc];
        } else if (EPI == EPI_DIV) {
            return v * bias[rr];
        }
        return v;
    };

    #pragma unroll
    for (int i = 0; i < MT; i++) {
        #pragma unroll
        for (int j = 0; j < NT; j++) {
            int rr = row0 + wm * WM + i * 16 + lr;
            int cc = col0 + wn * WN + j * 8 + 2 * lc;
            float e00 = epi(acc[i][j][0], rr, cc);
            float e01 = epi(acc[i][j][1], rr, cc + 1);
            float e10 = epi(acc[i][j][2], rr + 8, cc);
            float e11 = epi(acc[i][j][3], rr + 8, cc + 1);
            if (WF32) {
                *(float2*)(C + (size_t)rr * N + cc)       = make_float2(e00, e01);
                *(float2*)(C + (size_t)(rr + 8) * N + cc) = make_float2(e10, e11);
            }
            if (WPACK) {
                unsigned h, l;
                split2(e00, e01, h, l);
                size_t w0 = (size_t)rr * (N >> 1) + (cc >> 1);
                Ch[w0] = h; Cl[w0] = l;
                split2(e10, e11, h, l);
                size_t w1 = (size_t)(rr + 8) * (N >> 1) + (cc >> 1);
                Ch[w1] = h; Cl[w1] = l;
            }
        }
    }
}

// ---------------- kv partials: split over S ----------------
__global__ void __launch_bounds__(256)
kv_kernel(const float* __restrict__ Kp, const float* __restrict__ V,
          float* __restrict__ KVp)
{
    int b  = blockIdx.y;
    int f0 = blockIdx.x * 64;
    int sp = blockIdx.z;
    const float* Kb = Kp + (size_t)b * SS * PP;
    const float* Vb = V  + (size_t)b * SS * EE;

    __shared__ float Ks[32 * 64];
    __shared__ float Vs[32 * 64];
    int tid = threadIdx.x;
    int tx = tid % 16, ty = tid / 16;

    float acc[4][4];
    #pragma unroll
    for (int i = 0; i < 4; i++)
        #pragma unroll
        for (int j = 0; j < 4; j++) acc[i][j] = 0.f;

    int sbeg = sp * (SS / NSPLIT), send = sbeg + (SS / NSPLIT);
    for (int s0 = sbeg; s0 < send; s0 += 32) {
        #pragma unroll
        for (int i = 0; i < 2; i++) {
            int idx = tid + i * 256;
            int r = idx / 16, c4 = idx % 16;
            *(float4*)(Ks + r * 64 + c4 * 4) =
                *(const float4*)(Kb + (size_t)(s0 + r) * PP + c4 * 4);
            *(float4*)(Vs + r * 64 + c4 * 4) =
                *(const float4*)(Vb + (size_t)(s0 + r) * EE + f0 + c4 * 4);
        }
        __syncthreads();
        #pragma unroll
        for (int k = 0; k < 32; k++) {
            float rp[4], rv[4];
            #pragma unroll
            for (int i = 0; i < 4; i++) rp[i] = Ks[k * 64 + ty * 4 + i];
            #pragma unroll
            for (int j = 0; j < 4; j++) rv[j] = Vs[k * 64 + tx * 4 + j];
            #pragma unroll
            for (int i = 0; i < 4; i++)
                #pragma unroll
                for (int j = 0; j < 4; j++)
                    acc[i][j] = fmaf(rp[i], rv[j], acc[i][j]);
        }
        __syncthreads();
    }
    float* out = KVp + (size_t)sp * BB * PP * EE;
    #pragma unroll
    for (int i = 0; i < 4; i++)
        #pragma unroll
        for (int j = 0; j < 4; j++)
            out[((size_t)b * PP + ty * 4 + i) * EE + f0 + tx * 4 + j] = acc[i][j];
}

__global__ void reduce_kv(const float* __restrict__ KVp, float* __restrict__ KV) {
    size_t idx = (size_t)blockIdx.x * 256 + threadIdx.x;
    float s = 0.f;
    #pragma unroll
    for (int sp = 0; sp < NSPLIT; sp++)
        s += KVp[(size_t)sp * BB * PP * EE + idx];
    KV[idx] = s;
}

// ---------------- z partials ----------------
__global__ void z_kernel(const float* __restrict__ Kp, float* __restrict__ Zp) {
    int b = blockIdx.x, sp = blockIdx.y;
    int tid = threadIdx.x;
    int p = tid & 63, g = tid >> 6;
    const float* Kb = Kp + (size_t)b * SS * PP;
    float acc = 0.f;
    int sbeg = sp * (SS / NSPLIT), send = sbeg + (SS / NSPLIT);
    for (int s = sbeg + g; s < send; s += 4) acc += Kb[(size_t)s * PP + p];
    __shared__ float smem[256];
    smem[tid] = acc;
    __syncthreads();
    if (g == 0)
        Zp[(size_t)sp * BB * PP + b * PP + p] =
            smem[p] + smem[64 + p] + smem[128 + p] + smem[192 + p];
}

__global__ void reduce_z(const float* __restrict__ Zp, float* __restrict__ Z) {
    int idx = blockIdx.x * 256 + threadIdx.x;
    if (idx < BB * PP) {
        float s = 0.f;
        #pragma unroll
        for (int sp = 0; sp < NSPLIT; sp++) s += Zp[sp * BB * PP + idx];
        Z[idx] = s;
    }
}

// ---------------- den: inv[row] = 1/(phi_q[row] . z[b] + eps) ----------------
__global__ void den_kernel(const float* __restrict__ Q,
                           const float* __restrict__ Z,
                           float* __restrict__ inv) {
    int row  = blockIdx.x * 8 + (threadIdx.x >> 5);
    int lane = threadIdx.x & 31;
    int b    = row >> 12;                  // / SS
    const float* q = Q + (size_t)row * PP;
    const float* z = Z + b * PP;
    float s = q[lane] * z[lane] + q[lane + 32] * z[lane + 32];
    #pragma unroll
    for (int o = 16; o; o >>= 1) s += __shfl_xor_sync(0xffffffffu, s, o);
    if (lane == 0) inv[row] = 1.f / (s + 1e-6f);
}

// ---------------- layernorm: read fp32, write packed ----------------
__global__ void ln_kernel(const float* __restrict__ X,
                          const float* __restrict__ gam,
                          const float* __restrict__ bet,
                          unsigned* __restrict__ Oh, unsigned* __restrict__ Ol) {
    int row = blockIdx.x;
    const float* xr = X + (size_t)row * EE;
    int tid = threadIdx.x;                 // 128
    float4 v = ((const float4*)xr)[tid];
    float s = v.x + v.y + v.z + v.w;
    float q = v.x * v.x + v.y * v.y + v.z * v.z + v.w * v.w;
    #pragma unroll
    for (int o = 16; o; o >>= 1) {
        s += __shfl_xor_sync(0xffffffffu, s, o);
        q += __shfl_xor_sync(0xffffffffu, q, o);
    }
    __shared__ float ss[4], qq[4];
    int w = tid >> 5;
    if ((tid & 31) == 0) { ss[w] = s; qq[w] = q; }
    __syncthreads();
    s = ss[0] + ss[1] + ss[2] + ss[3];
    q = qq[0] + qq[1] + qq[2] + qq[3];
    float mu  = s * (1.f / EE);
    float var = q * (1.f / EE) - mu * mu;
    float inv = rsqrtf(var + 1e-5f);
    float4 g4 = ((const float4*)gam)[tid];
    float4 b4 = ((const float4*)bet)[tid];
    float o0 = (v.x - mu) * inv * g4.x + b4.x;
    float o1 = (v.y - mu) * inv * g4.y + b4.y;
    float o2 = (v.z - mu) * inv * g4.z + b4.z;
    float o3 = (v.w - mu) * inv * g4.w + b4.w;
    unsigned h0, l0, h1, l1;
    split2(o0, o1, h0, l0);
    split2(o2, o3, h1, l1);
    size_t wo = (size_t)row * (EE / 2) + 2 * tid;
    Oh[wo] = h0; Oh[wo + 1] = h1;
    Ol[wo] = l0; Ol[wo + 1] = l1;
}

// ---------------- head ----------------
__global__ void head_kernel(const float* __restrict__ Hm,
                            const float* __restrict__ Wh1,
                            const float* __restrict__ bh1,
                            const float* __restrict__ Wh2,
                            const float* __restrict__ bh2,
                            float* __restrict__ out) {
    int b = blockIdx.x;
    int tid = threadIdx.x;
    const float* hr = Hm + (size_t)b * SS * EE;
    float acc = bh1[tid];
    for (int e = 0; e < EE; e++) acc = fmaf(hr[e], Wh1[e * HH + tid], acc);
    acc = fmaxf(acc, 0.f);
    __shared__ float hid[HH];
    hid[tid] = acc;
    __syncthreads();
    if (tid < CC) {
        float a = bh2[tid];
        for (int h = 0; h < HH; h++) a = fmaf(hid[h], Wh2[h * CC + tid], a);
        out[b * CC + tid] = a;
    }
}

// ---------------- launch ----------------
static size_t gemm_smem(int BM, int BN) {
    return (size_t)(3 * (BM * 20 * 2 + BN * 20 * 2)) * 4;
}

extern "C" void kernel_launch(void* const* d_in, const int* in_sizes, int n_in,
                              void* d_out, int out_size) {
    const int*   x    = (const int*)  d_in[0];
    const float* emb  = (const float*)d_in[1];
    const float* pos  = (const float*)d_in[2];
    const float* Wq   = (const float*)d_in[3];
    const float* Wk   = (const float*)d_in[4];
    const float* Wv   = (const float*)d_in[5];
    const float* Wo   = (const float*)d_in[6];
    const float* ln_g = (const float*)d_in[7];
    const float* ln_b = (const float*)d_in[8];
    const float* W1   = (const float*)d_in[9];
    const float* b1   = (const float*)d_in[10];
    const float* W2   = (const float*)d_in[11];
    const float* b2   = (const float*)d_in[12];
    const float* Wh1  = (const float*)d_in[13];
    const float* bh1  = (const float*)d_in[14];
    const float* Wh2  = (const float*)d_in[15];
    const float* bh2  = (const float*)d_in[16];
    float* out = (float*)d_out;

    float *H, *A, *V, *Q, *Kq, *KV, *KVp, *Z, *Zp, *DEN;
    cudaGetSymbolAddress((void**)&H,   g_H);
    cudaGetSymbolAddress((void**)&A,   g_A);
    cudaGetSymbolAddress((void**)&V,   g_V);
    cudaGetSymbolAddress((void**)&Q,   g_Q);
    cudaGetSymbolAddress((void**)&Kq,  g_K);
    cudaGetSymbolAddress((void**)&KV,  g_KV);
    cudaGetSymbolAddress((void**)&KVp, g_KVp);
    cudaGetSymbolAddress((void**)&Z,   g_Z);
    cudaGetSymbolAddress((void**)&Zp,  g_Zp);
    cudaGetSymbolAddress((void**)&DEN, g_DEN);

    unsigned *Hh, *Hl, *NMh, *NMl, *LNh, *LNl, *Mbh, *Mbl, *Qh, *Ql, *KVTh, *KVTl;
    cudaGetSymbolAddress((void**)&Hh,  g_Hh);  cudaGetSymbolAddress((void**)&Hl,  g_Hl);
    cudaGetSymbolAddress((void**)&NMh, g_NMh); cudaGetSymbolAddress((void**)&NMl, g_NMl);
    cudaGetSymbolAddress((void**)&LNh, g_LNh); cudaGetSymbolAddress((void**)&LNl, g_LNl);
    cudaGetSymbolAddress((void**)&Mbh, g_Mbh); cudaGetSymbolAddress((void**)&Mbl, g_Mbl);
    cudaGetSymbolAddress((void**)&Qh,  g_Qh);  cudaGetSymbolAddress((void**)&Ql,  g_Ql);
    cudaGetSymbolAddress((void**)&KVTh, g_KVTh); cudaGetSymbolAddress((void**)&KVTl, g_KVTl);

    unsigned *Wqh, *Wql, *Wkh, *Wkl, *Wvh, *Wvl, *Woh, *Wol, *W1h, *W1l, *W2h, *W2l;
    cudaGetSymbolAddress((void**)&Wqh, g_Wqh); cudaGetSymbolAddress((void**)&Wql, g_Wql_);
    cudaGetSymbolAddress((void**)&Wkh, g_Wkh); cudaGetSymbolAddress((void**)&Wkl, g_Wkl_);
    cudaGetSymbolAddress((void**)&Wvh, g_Wvh); cudaGetSymbolAddress((void**)&Wvl, g_Wvl_);
    cudaGetSymbolAddress((void**)&Woh, g_Woh); cudaGetSymbolAddress((void**)&Wol, g_Wol_);
    cudaGetSymbolAddress((void**)&W1h, g_W1h); cudaGetSymbolAddress((void**)&W1l, g_W1l_);
    cudaGetSymbolAddress((void**)&W2h, g_W2h); cudaGetSymbolAddress((void**)&W2l, g_W2l_);

    const size_t smQK  = gemm_smem(128, 64);    //  92,160 B
    const size_t smBIG = gemm_smem(128, 256);   // 184,320 B
    cudaFuncSetAttribute(gemm_pk<128, 64, 32, 32, EPI_PHI, true, true, false>,
                         cudaFuncAttributeMaxDynamicSharedMemorySize, (int)smQK);
    cudaFuncSetAttribute(gemm_pk<128, 64, 32, 32, EPI_PHI, true, false, false>,
                         cudaFuncAttributeMaxDynamicSharedMemorySize, (int)smQK);
    cudaFuncSetAttribute(gemm_pk<128, 256, 64, 64, EPI_NONE, true, false, false>,
                         cudaFuncAttributeMaxDynamicSharedMemorySize, (int)smBIG);
    cudaFuncSetAttribute(gemm_pk<128, 256, 64, 64, EPI_DIV, false, true, true>,
                         cudaFuncAttributeMaxDynamicSharedMemorySize, (int)smBIG);
    cudaFuncSetAttribute(gemm_pk<128, 256, 64, 64, EPI_GELU, false, true, false>,
                         cudaFuncAttributeMaxDynamicSharedMemorySize, (int)smBIG);
    cudaFuncSetAttribute(gemm_pk<128, 256, 64, 64, EPI_RES, true, true, false>,
                         cudaFuncAttributeMaxDynamicSharedMemorySize, (int)smBIG);

    // one-time weight transpose+split (all layers)
    dim3 wt(32, 8);
    wsplit_kernel<<<dim3(PP / 32, EE / 32, LL), wt>>>(Wq, Wqh, Wql, EE, PP);
    wsplit_kernel<<<dim3(PP / 32, EE / 32, LL), wt>>>(Wk, Wkh, Wkl, EE, PP);
    wsplit_kernel<<<dim3(EE / 32, EE / 32, LL), wt>>>(Wv, Wvh, Wvl, EE, EE);
    wsplit_kernel<<<dim3(EE / 32, EE / 32, LL), wt>>>(Wo, Woh, Wol, EE, EE);
    wsplit_kernel<<<dim3(FF / 32, EE / 32, LL), wt>>>(W1, W1h, W1l, EE, FF);
    wsplit_kernel<<<dim3(EE / 32, FF / 32, LL), wt>>>(W2, W2h, W2l, FF, EE);

    embed_kernel<<<MROWS, 128>>>(x, emb, pos, H, Hh, Hl);

    for (int l = 0; l < LL; l++) {
        size_t oQK = (size_t)l * PP * (EE / 2);
        size_t oV  = (size_t)l * EE * (EE / 2);
        size_t oW1 = (size_t)l * FF * (EE / 2);
        size_t oW2 = (size_t)l * EE * (FF / 2);

        // phi_q: fp32 (for den) + packed (for num GEMM)
        gemm_pk<128, 64, 32, 32, EPI_PHI, true, true, false>
            <<<dim3(PP / 64, MROWS / 128), 256, smQK>>>(
                MROWS, PP, EE, Hh, Hl, Wqh + oQK, Wql + oQK,
                nullptr, nullptr, Q, Qh, Ql);
        gemm_pk<128, 64, 32, 32, EPI_PHI, true, false, false>
            <<<dim3(PP / 64, MROWS / 128), 256, smQK>>>(
                MROWS, PP, EE, Hh, Hl, Wkh + oQK, Wkl + oQK,
                nullptr, nullptr, Kq, nullptr, nullptr);
        gemm_pk<128, 256, 64, 64, EPI_NONE, true, false, false>
            <<<dim3(EE / 256, MROWS / 128), 256, smBIG>>>(
                MROWS, EE, EE, Hh, Hl, Wvh + oV, Wvl + oV,
                nullptr, nullptr, V, nullptr, nullptr);

        kv_kernel<<<dim3(EE / 64, BB, NSPLIT), 256>>>(Kq, V, KVp);
        z_kernel<<<dim3(BB, NSPLIT), 256>>>(Kq, Zp);
        reduce_kv<<<(BB * PP * EE) / 256, 256>>>(KVp, KV);
        reduce_z<<<2, 256>>>(Zp, Z);
        // KV [b][P][E] -> packed transposed [b][E][P/2]
        wsplit_kernel<<<dim3(EE / 32, PP / 32, BB), wt>>>(KV, KVTh, KVTl, PP, EE);
        den_kernel<<<MROWS / 8, 256>>>(Q, Z, DEN);

        // num/den via tensor GEMM: attn = (phi_q @ KV) * inv[row], packed out
        gemm_pk<128, 256, 64, 64, EPI_DIV, false, true, true>
            <<<dim3(EE / 256, MROWS / 128), 256, smBIG>>>(
                MROWS, EE, PP, Qh, Ql, KVTh, KVTl,
                DEN, nullptr, nullptr, NMh, NMl);

        gemm_pk<128, 256, 64, 64, EPI_NONE, true, false, false>
            <<<dim3(EE / 256, MROWS / 128), 256, smBIG>>>(
                MROWS, EE, EE, NMh, NMl, Woh + oV, Wol + oV,
                nullptr, nullptr, A, nullptr, nullptr);

        ln_kernel<<<MROWS, 128>>>(A, ln_g + (size_t)l * EE, ln_b + (size_t)l * EE,
                                  LNh, LNl);

        gemm_pk<128, 256, 64, 64, EPI_GELU, false, true, false>
            <<<dim3(FF / 256, MROWS / 128), 256, smBIG>>>(
                MROWS, FF, EE, LNh, LNl, W1h + oW1, W1l + oW1,
                b1 + (size_t)l * FF, nullptr, nullptr, Mbh, Mbl);
        gemm_pk<128, 256, 64, 64, EPI_RES, true, true, false>
            <<<dim3(EE / 256, MROWS / 128), 256, smBIG>>>(
                MROWS, EE, FF, Mbh, Mbl, W2h + oW2, W2l + oW2,
                b2 + (size_t)l * EE, H, H, Hh, Hl);
    }

    head_kernel<<<BB, HH>>>(H, Wh1, bh1, Wh2, bh2, out);
}